// round 3
// baseline (speedup 1.0000x reference)
#include <cuda_runtime.h>
#include <math.h>

// Problem constants
#define S_LEN  2048
#define HDIM   4096     // hidden = NH*HD
#define NHEADS 32
#define HEADD  128

// Scratch (device globals: allocation-free rule)
__device__ float g_Q[S_LEN * HDIM];   // 32 MB
__device__ float g_K[S_LEN * HDIM];   // 32 MB
__device__ float g_V[S_LEN * HDIM];   // 32 MB
__device__ float g_A[S_LEN * HDIM];   // 32 MB (attention output, pre-O-proj)

// ---------------------------------------------------------------------------
// GEMM: C[m,n] = sum_k A[m,k] * B[n,k]    (A: [M,K] row-major, B: [N,K] row-major)
// This matches torch Linear (x @ W.T) with W stored [out, in] row-major.
// 128x128 tile, BK=8, 256 threads, 8x8 per thread, float4 global + smem.
// ---------------------------------------------------------------------------
__global__ void __launch_bounds__(256) sgemm_nt(const float* __restrict__ A,
                                                const float* __restrict__ B,
                                                float* __restrict__ C,
                                                int M, int N, int K)
{
    __shared__ float As[8][128];
    __shared__ float Bs[8][128];

    const int m0 = blockIdx.y * 128;
    const int n0 = blockIdx.x * 128;
    const int t  = threadIdx.x;
    const int tx = t & 15;
    const int ty = t >> 4;

    // global load mapping: each thread loads one float4 of A and one of B per BK step
    const int lrow = t >> 1;          // 0..127
    const int lcol = (t & 1) << 2;    // 0 or 4
    const float* Ag = A + (size_t)(m0 + lrow) * K + lcol;
    const float* Bg = B + (size_t)(n0 + lrow) * K + lcol;

    float acc[8][8];
#pragma unroll
    for (int i = 0; i < 8; ++i)
#pragma unroll
        for (int j = 0; j < 8; ++j) acc[i][j] = 0.0f;

    for (int k0 = 0; k0 < K; k0 += 8) {
        float4 av = *(const float4*)(Ag + k0);
        float4 bv = *(const float4*)(Bg + k0);
        As[lcol + 0][lrow] = av.x;
        As[lcol + 1][lrow] = av.y;
        As[lcol + 2][lrow] = av.z;
        As[lcol + 3][lrow] = av.w;
        Bs[lcol + 0][lrow] = bv.x;
        Bs[lcol + 1][lrow] = bv.y;
        Bs[lcol + 2][lrow] = bv.z;
        Bs[lcol + 3][lrow] = bv.w;
        __syncthreads();

#pragma unroll
        for (int kk = 0; kk < 8; ++kk) {
            float4 a0 = *(const float4*)&As[kk][ty * 8];
            float4 a1 = *(const float4*)&As[kk][ty * 8 + 4];
            float4 b0 = *(const float4*)&Bs[kk][tx * 8];
            float4 b1 = *(const float4*)&Bs[kk][tx * 8 + 4];
            float ar[8] = {a0.x, a0.y, a0.z, a0.w, a1.x, a1.y, a1.z, a1.w};
            float br[8] = {b0.x, b0.y, b0.z, b0.w, b1.x, b1.y, b1.z, b1.w};
#pragma unroll
            for (int i = 0; i < 8; ++i)
#pragma unroll
                for (int j = 0; j < 8; ++j)
                    acc[i][j] = fmaf(ar[i], br[j], acc[i][j]);
        }
        __syncthreads();
    }

#pragma unroll
    for (int i = 0; i < 8; ++i) {
        size_t row = (size_t)(m0 + ty * 8 + i);
        float4 c0 = make_float4(acc[i][0], acc[i][1], acc[i][2], acc[i][3]);
        float4 c1 = make_float4(acc[i][4], acc[i][5], acc[i][6], acc[i][7]);
        *(float4*)&C[row * N + n0 + tx * 8]     = c0;
        *(float4*)&C[row * N + n0 + tx * 8 + 4] = c1;
    }
}

// ---------------------------------------------------------------------------
// RoPE in-place on Q and K. One thread per (s, head, j<64) pair.
// out[d]    = x[d]*cos - x[d+64]*sin   (d < 64)
// out[d+64] = x[d+64]*cos + x[d]*sin
// cos/sin at angle = pos * (10000^{-j/64})
// ---------------------------------------------------------------------------
__global__ void rope_kernel(float* __restrict__ Q, float* __restrict__ K,
                            const int* __restrict__ pos)
{
    int idx = blockIdx.x * 256 + threadIdx.x;
    const int total = S_LEN * NHEADS * 64;
    if (idx >= total) return;
    int j = idx & 63;
    int h = (idx >> 6) & (NHEADS - 1);
    int s = idx >> 11;  // 64*32 = 2048 per s

    int p = pos[s];
    float inv = 1.0f / powf(10000.0f, (float)j * (1.0f / 64.0f));
    float ang = (float)p * inv;
    float sn, cs;
    sincosf(ang, &sn, &cs);

    size_t base = (size_t)s * HDIM + (size_t)h * HEADD + j;
    float q1 = Q[base], q2 = Q[base + 64];
    Q[base]      = q1 * cs - q2 * sn;
    Q[base + 64] = q2 * cs + q1 * sn;
    float k1 = K[base], k2 = K[base + 64];
    K[base]      = k1 * cs - k2 * sn;
    K[base + 64] = k2 * cs + k1 * sn;
}

// ---------------------------------------------------------------------------
// Flash attention (causal), fp32. One CTA per (q-block of 64, head).
// smem: Qts[128][68] (Q transposed, scaled), KV buffer (K transposed [128][68],
// then V row-major [64][132]), Ss[64][68] scores/probs, m/l/scale rows.
// 256 threads: scores 4x4/thread (16x16 grid over 64x64), PV 4x8/thread
// (rows ty*4+i, cols tx*8+j over 64x128).
// ---------------------------------------------------------------------------
#define NEG_BIG (-3.0e38f)
#define FLASH_SMEM ((128 * 68 * 2 + 64 * 68 + 192) * 4)   // 87808 bytes

__global__ void __launch_bounds__(256) flash_attn(const float* __restrict__ Q,
                                                  const float* __restrict__ K,
                                                  const float* __restrict__ V,
                                                  float* __restrict__ O)
{
    extern __shared__ float sm[];
    float* Qts  = sm;                   // [128][68]
    float* KV   = Qts + 128 * 68;       // K-trans [128][68]  /  V [64][132]
    float* Ss   = KV + 128 * 68;        // [64][68]
    float* mrow = Ss + 64 * 68;         // [64]
    float* lrow = mrow + 64;            // [64]
    float* srow = lrow + 64;            // [64]

    const int qb = blockIdx.x;
    const int h  = blockIdx.y;
    const int q0 = qb * 64;
    const int t  = threadIdx.x;
    const int tx = t & 15;
    const int ty = t >> 4;
    const float scale = 0.08838834764831843f;  // 1/sqrt(128)

    // Load Q tile transposed & pre-scaled: Qts[d][r]
    for (int i = t; i < 64 * 32; i += 256) {
        int r  = i >> 5;
        int c4 = (i & 31) << 2;
        float4 v = *(const float4*)&Q[(size_t)(q0 + r) * HDIM + (size_t)h * HEADD + c4];
        Qts[(c4 + 0) * 68 + r] = v.x * scale;
        Qts[(c4 + 1) * 68 + r] = v.y * scale;
        Qts[(c4 + 2) * 68 + r] = v.z * scale;
        Qts[(c4 + 3) * 68 + r] = v.w * scale;
    }
    if (t < 64) { mrow[t] = NEG_BIG; lrow[t] = 0.0f; }

    float o[4][8];
#pragma unroll
    for (int i = 0; i < 4; ++i)
#pragma unroll
        for (int j = 0; j < 8; ++j) o[i][j] = 0.0f;

    for (int kb = 0; kb <= qb; ++kb) {
        const int k0 = kb * 64;
        __syncthreads();  // previous iteration's PV reads of KV are done

        // Load K tile transposed: KV[d][c]
        for (int i = t; i < 64 * 32; i += 256) {
            int r  = i >> 5;
            int c4 = (i & 31) << 2;
            float4 v = *(const float4*)&K[(size_t)(k0 + r) * HDIM + (size_t)h * HEADD + c4];
            KV[(c4 + 0) * 68 + r] = v.x;
            KV[(c4 + 1) * 68 + r] = v.y;
            KV[(c4 + 2) * 68 + r] = v.z;
            KV[(c4 + 3) * 68 + r] = v.w;
        }
        __syncthreads();  // Qts (first iter) + K ready

        // Scores: S[r][c] = q_r . k_c, 4x4 per thread
        float sacc[4][4];
#pragma unroll
        for (int i = 0; i < 4; ++i)
#pragma unroll
            for (int j = 0; j < 4; ++j) sacc[i][j] = 0.0f;

#pragma unroll 4
        for (int d = 0; d < 128; ++d) {
            float4 qv = *(const float4*)&Qts[d * 68 + (ty << 2)];
            float4 kv = *(const float4*)&KV[d * 68 + (tx << 2)];
            float qa[4] = {qv.x, qv.y, qv.z, qv.w};
            float ka[4] = {kv.x, kv.y, kv.z, kv.w};
#pragma unroll
            for (int i = 0; i < 4; ++i)
#pragma unroll
                for (int j = 0; j < 4; ++j)
                    sacc[i][j] = fmaf(qa[i], ka[j], sacc[i][j]);
        }

        const bool diag = (kb == qb);
#pragma unroll
        for (int i = 0; i < 4; ++i) {
            int rg = ty * 4 + i;
#pragma unroll
            for (int j = 0; j < 4; ++j) {
                int cg = tx * 4 + j;
                float v = sacc[i][j];
                if (diag && cg > rg) v = NEG_BIG;   // causal mask
                Ss[rg * 68 + cg] = v;
            }
        }
        __syncthreads();  // scores in Ss; K reads done (KV reusable)

        // Online softmax: 4 threads per row (row = t>>2, quarter = t&3)
        {
            int r  = t >> 2;
            int qd = t & 3;
            float* srw = &Ss[r * 68 + qd * 16];
            float vals[16];
            float mx = NEG_BIG;
#pragma unroll
            for (int i = 0; i < 16; ++i) { vals[i] = srw[i]; mx = fmaxf(mx, vals[i]); }
            mx = fmaxf(mx, __shfl_xor_sync(0xffffffffu, mx, 1));
            mx = fmaxf(mx, __shfl_xor_sync(0xffffffffu, mx, 2));
            float mold = mrow[r];
            float mnew = fmaxf(mold, mx);
            float sum = 0.0f;
#pragma unroll
            for (int i = 0; i < 16; ++i) {
                float p = __expf(vals[i] - mnew);
                srw[i] = p;
                sum += p;
            }
            sum += __shfl_xor_sync(0xffffffffu, sum, 1);
            sum += __shfl_xor_sync(0xffffffffu, sum, 2);
            float corr = __expf(mold - mnew);   // 0 on first block (underflow)
            if (qd == 0) {
                mrow[r] = mnew;
                lrow[r] = lrow[r] * corr + sum;
                srow[r] = corr;
            }
        }

        // Load V tile row-major into KV: KV[r*132 + c]
        for (int i = t; i < 64 * 32; i += 256) {
            int r  = i >> 5;
            int c4 = (i & 31) << 2;
            *(float4*)&KV[r * 132 + c4] =
                *(const float4*)&V[(size_t)(k0 + r) * HDIM + (size_t)h * HEADD + c4];
        }
        __syncthreads();  // P in Ss, V in KV, srow/lrow/mrow published

        // Rescale accumulators, then O += P @ V
        float corr[4];
#pragma unroll
        for (int i = 0; i < 4; ++i) corr[i] = srow[ty * 4 + i];
#pragma unroll
        for (int i = 0; i < 4; ++i)
#pragma unroll
            for (int j = 0; j < 8; ++j) o[i][j] *= corr[i];

#pragma unroll 2
        for (int kk = 0; kk < 64; ++kk) {
            float4 va = *(const float4*)&KV[kk * 132 + (tx << 3)];
            float4 vb = *(const float4*)&KV[kk * 132 + (tx << 3) + 4];
            float vv[8] = {va.x, va.y, va.z, va.w, vb.x, vb.y, vb.z, vb.w};
            float pr[4];
#pragma unroll
            for (int i = 0; i < 4; ++i) pr[i] = Ss[(ty * 4 + i) * 68 + kk];
#pragma unroll
            for (int i = 0; i < 4; ++i)
#pragma unroll
                for (int j = 0; j < 8; ++j)
                    o[i][j] = fmaf(pr[i], vv[j], o[i][j]);
        }
    }

    // Epilogue: normalize and store
    float linv[4];
#pragma unroll
    for (int i = 0; i < 4; ++i) linv[i] = 1.0f / lrow[ty * 4 + i];
#pragma unroll
    for (int i = 0; i < 4; ++i) {
        size_t base = (size_t)(q0 + ty * 4 + i) * HDIM + (size_t)h * HEADD + (tx << 3);
        float4 r0 = make_float4(o[i][0] * linv[i], o[i][1] * linv[i],
                                o[i][2] * linv[i], o[i][3] * linv[i]);
        float4 r1 = make_float4(o[i][4] * linv[i], o[i][5] * linv[i],
                                o[i][6] * linv[i], o[i][7] * linv[i]);
        *(float4*)&O[base]     = r0;
        *(float4*)&O[base + 4] = r1;
    }
}

// ---------------------------------------------------------------------------
// Launch
// ---------------------------------------------------------------------------
extern "C" void kernel_launch(void* const* d_in, const int* in_sizes, int n_in,
                              void* d_out, int out_size)
{
    (void)in_sizes; (void)n_in; (void)out_size;

    const float* X   = (const float*)d_in[0];   // hidden_states [1,2048,4096]
    // d_in[1] attention_mask: causal by construction -> handled analytically
    const int*   pos = (const int*)d_in[2];     // position_ids [1,2048]
    const float* Wq  = (const float*)d_in[3];   // [4096,4096] row-major [out][in]
    const float* Wk  = (const float*)d_in[4];
    const float* Wv  = (const float*)d_in[5];
    const float* Wo  = (const float*)d_in[6];
    float* out = (float*)d_out;                 // [1,2048,4096] fp32

    float *Qd, *Kd, *Vd, *Ad;
    cudaGetSymbolAddress((void**)&Qd, g_Q);
    cudaGetSymbolAddress((void**)&Kd, g_K);
    cudaGetSymbolAddress((void**)&Vd, g_V);
    cudaGetSymbolAddress((void**)&Ad, g_A);

    cudaFuncSetAttribute(flash_attn, cudaFuncAttributeMaxDynamicSharedMemorySize,
                         FLASH_SMEM);

    dim3 gemm_grid(HDIM / 128, S_LEN / 128);   // (32, 16)

    // QKV projections
    sgemm_nt<<<gemm_grid, 256>>>(X, Wq, Qd, S_LEN, HDIM, HDIM);
    sgemm_nt<<<gemm_grid, 256>>>(X, Wk, Kd, S_LEN, HDIM, HDIM);
    sgemm_nt<<<gemm_grid, 256>>>(X, Wv, Vd, S_LEN, HDIM, HDIM);

    // RoPE on Q and K (in place)
    {
        int total = S_LEN * NHEADS * 64;
        rope_kernel<<<(total + 255) / 256, 256>>>(Qd, Kd, pos);
    }

    // Causal flash attention per (q-block, head)
    flash_attn<<<dim3(S_LEN / 64, NHEADS), 256, FLASH_SMEM>>>(Qd, Kd, Vd, Ad);

    // Output projection
    sgemm_nt<<<gemm_grid, 256>>>(Ad, Wo, out, S_LEN, HDIM, HDIM);
}

// round 5
// speedup vs baseline: 2.0677x; 2.0677x over previous
#include <cuda_runtime.h>
#include <cuda_bf16.h>
#include <math.h>
#include <stdint.h>

// Problem constants
#define S_LEN  2048
#define HDIM   4096     // hidden = NH*HD
#define NHEADS 32
#define HEADD  128

#define K2     12288    // 3 * HDIM (bf16x2 split: [Ah|Ah|Al] x [Bh|Bl|Bh])

// Scratch (device globals: allocation-free rule)
__device__ float g_Q[S_LEN * HDIM];
__device__ float g_K[S_LEN * HDIM];
__device__ float g_V[S_LEN * HDIM];
__device__ float g_A[S_LEN * HDIM];
__device__ __nv_bfloat16 g_A2[S_LEN * K2];
__device__ __nv_bfloat16 g_W2q[HDIM * K2];
__device__ __nv_bfloat16 g_W2k[HDIM * K2];
__device__ __nv_bfloat16 g_W2v[HDIM * K2];
__device__ __nv_bfloat16 g_W2o[HDIM * K2];

// ===========================================================================
// PTX helpers (base PTX only — no 'a'-suffix features)
// ===========================================================================
__device__ __forceinline__ uint32_t smem_u32(const void* p) {
    uint32_t a;
    asm("{ .reg .u64 t; cvta.to.shared.u64 t, %1; cvt.u32.u64 %0, t; }" : "=r"(a) : "l"(p));
    return a;
}
__device__ __forceinline__ void cp_async16(uint32_t dst, const void* src) {
    asm volatile("cp.async.cg.shared.global [%0], [%1], 16;" :: "r"(dst), "l"(src));
}
__device__ __forceinline__ void cp_commit() {
    asm volatile("cp.async.commit_group;" ::: "memory");
}
template <int N> __device__ __forceinline__ void cp_wait() {
    asm volatile("cp.async.wait_group %0;" :: "n"(N) : "memory");
}
__device__ __forceinline__ void ldsm_x4(uint32_t& r0, uint32_t& r1, uint32_t& r2,
                                        uint32_t& r3, uint32_t addr) {
    asm volatile("ldmatrix.sync.aligned.m8n8.x4.shared.b16 {%0,%1,%2,%3}, [%4];"
                 : "=r"(r0), "=r"(r1), "=r"(r2), "=r"(r3) : "r"(addr));
}
__device__ __forceinline__ void mma16816(float* c, const uint32_t* a, const uint32_t* b) {
    asm volatile(
        "mma.sync.aligned.m16n8k16.row.col.f32.bf16.bf16.f32 "
        "{%0,%1,%2,%3}, {%4,%5,%6,%7}, {%8,%9}, {%0,%1,%2,%3};"
        : "+f"(c[0]), "+f"(c[1]), "+f"(c[2]), "+f"(c[3])
        : "r"(a[0]), "r"(a[1]), "r"(a[2]), "r"(a[3]), "r"(b[0]), "r"(b[1]));
}

// ===========================================================================
// fp32 -> bf16x2 split kernels
// ===========================================================================
__device__ __forceinline__ uint32_t pkb(__nv_bfloat16 a, __nv_bfloat16 b) {
    __nv_bfloat162 t = __halves2bfloat162(a, b);
    return *reinterpret_cast<uint32_t*>(&t);
}

__global__ void __launch_bounds__(256) split_bf16(const float* __restrict__ src,
                                                  __nv_bfloat16* __restrict__ dst,
                                                  int total4)
{
    int i = blockIdx.x * 256 + threadIdx.x;
    if (i >= total4) return;
    int row = i >> 10;
    int c4  = (i & 1023) << 2;
    float4 v = ((const float4*)src)[i];
    float in[4] = {v.x, v.y, v.z, v.w};
    __nv_bfloat16 h[4], l[4];
#pragma unroll
    for (int j = 0; j < 4; ++j) {
        h[j] = __float2bfloat16_rn(in[j]);
        l[j] = __float2bfloat16_rn(in[j] - __bfloat162float(h[j]));
    }
    uint2 hh = make_uint2(pkb(h[0], h[1]), pkb(h[2], h[3]));
    uint2 ll = make_uint2(pkb(l[0], l[1]), pkb(l[2], l[3]));
    size_t b = (size_t)row * K2 + c4;
    *(uint2*)(dst + b)            = hh;   // seg0: hi (pairs with B hi)
    *(uint2*)(dst + b + HDIM)     = hh;   // seg1: hi (pairs with B lo)
    *(uint2*)(dst + b + 2 * HDIM) = ll;   // seg2: lo (pairs with B hi)
}

__global__ void __launch_bounds__(256) split_bf16_w(const float* __restrict__ src,
                                                    __nv_bfloat16* __restrict__ dst,
                                                    int total4)
{
    int i = blockIdx.x * 256 + threadIdx.x;
    if (i >= total4) return;
    int row = i >> 10;
    int c4  = (i & 1023) << 2;
    float4 v = ((const float4*)src)[i];
    float in[4] = {v.x, v.y, v.z, v.w};
    __nv_bfloat16 h[4], l[4];
#pragma unroll
    for (int j = 0; j < 4; ++j) {
        h[j] = __float2bfloat16_rn(in[j]);
        l[j] = __float2bfloat16_rn(in[j] - __bfloat162float(h[j]));
    }
    uint2 hh = make_uint2(pkb(h[0], h[1]), pkb(h[2], h[3]));
    uint2 ll = make_uint2(pkb(l[0], l[1]), pkb(l[2], l[3]));
    size_t b = (size_t)row * K2 + c4;
    *(uint2*)(dst + b)            = hh;   // seg0: hi
    *(uint2*)(dst + b + HDIM)     = ll;   // seg1: lo (pairs with A hi)
    *(uint2*)(dst + b + 2 * HDIM) = hh;   // seg2: hi (pairs with A lo)
}

// ===========================================================================
// mma.sync bf16 GEMM: C[2048,4096] = A2[2048,K2] @ B2[4096,K2]^T (fp32 out)
// CTA 128x128, BK=32, 256 threads (8 warps 2x4, warp tile 64x32).
// SMEM rows padded to 80B (5x16B, gcd(5,8)=1 -> conflict-free ldmatrix).
// 4-stage cp.async pipeline.
// ===========================================================================
#define BM 128
#define BN 128
#define BK 32
#define NITER   (K2 / BK)          // 384
#define GSTAGES 4
#define ROWB    80                 // padded row stride (32 bf16 = 64B data + 16B pad)
#define ASZ     (BM * ROWB)        // 10240
#define STAGE   (2 * ASZ)          // 20480
#define GSMEM   (GSTAGES * STAGE)  // 81920

__device__ __forceinline__ void g_load_stage(uint32_t sb,
                                             const __nv_bfloat16* __restrict__ A2,
                                             const __nv_bfloat16* __restrict__ B2,
                                             int m0, int n0, int k0, int t)
{
#pragma unroll
    for (int i = 0; i < 2; ++i) {
        int c   = t + (i << 8);
        int row = c >> 2;
        int kc  = c & 3;
        cp_async16(sb + row * ROWB + kc * 16,
                   A2 + (size_t)(m0 + row) * K2 + k0 + kc * 8);
    }
#pragma unroll
    for (int i = 0; i < 2; ++i) {
        int c   = t + (i << 8);
        int row = c >> 2;
        int kc  = c & 3;
        cp_async16(sb + ASZ + row * ROWB + kc * 16,
                   B2 + (size_t)(n0 + row) * K2 + k0 + kc * 8);
    }
    cp_commit();
}

__global__ void __launch_bounds__(256)
gemm_mma(const __nv_bfloat16* __restrict__ A2,
         const __nv_bfloat16* __restrict__ B2,
         float* __restrict__ C)
{
    extern __shared__ char smraw[];
    const uint32_t base = smem_u32(smraw);
    const int t    = threadIdx.x;
    const int wid  = t >> 5;
    const int lane = t & 31;
    const int m0   = blockIdx.y * BM;
    const int n0   = blockIdx.x * BN;
    const int wm   = (wid >> 2) * 64;   // warp m offset in tile
    const int wn   = (wid & 3) * 32;    // warp n offset in tile

    // per-lane ldmatrix row/col selectors
    const int rA   = lane & 15;          // A: row within 16, lanes 16-31 -> k8 half
    const int selA = lane >> 4;
    const int rB   = ((lane >> 4) << 3) | (lane & 7);   // B: n row (0-15)
    const int selB = (lane >> 3) & 1;                   // B: k8 half

    float acc[4][4][4];
#pragma unroll
    for (int mi = 0; mi < 4; ++mi)
#pragma unroll
        for (int nj = 0; nj < 4; ++nj)
#pragma unroll
            for (int q = 0; q < 4; ++q) acc[mi][nj][q] = 0.0f;

    // prologue: stages 0..2
#pragma unroll
    for (int it = 0; it < GSTAGES - 1; ++it)
        g_load_stage(base + it * STAGE, A2, B2, m0, n0, it * BK, t);

    for (int it = 0; it < NITER; ++it) {
        const int st = it & (GSTAGES - 1);
        cp_wait<GSTAGES - 2>();
        __syncthreads();

        const uint32_t stA = base + st * STAGE;
        const uint32_t stB = stA + ASZ;

#pragma unroll
        for (int kh = 0; kh < 2; ++kh) {
            uint32_t a[4][4];
#pragma unroll
            for (int mi = 0; mi < 4; ++mi)
                ldsm_x4(a[mi][0], a[mi][1], a[mi][2], a[mi][3],
                        stA + (uint32_t)((wm + mi * 16 + rA) * ROWB
                                         + (kh * 2 + selA) * 16));
            uint32_t b[2][4];
#pragma unroll
            for (int p = 0; p < 2; ++p)
                ldsm_x4(b[p][0], b[p][1], b[p][2], b[p][3],
                        stB + (uint32_t)((wn + p * 16 + rB) * ROWB
                                         + (kh * 2 + selB) * 16));
#pragma unroll
            for (int mi = 0; mi < 4; ++mi) {
#pragma unroll
                for (int nj = 0; nj < 4; ++nj) {
                    const uint32_t* bf = &b[nj >> 1][(nj & 1) << 1];
                    mma16816(acc[mi][nj], a[mi], bf);
                }
            }
        }

        const int j = it + GSTAGES - 1;
        if (j < NITER)
            g_load_stage(base + (j & (GSTAGES - 1)) * STAGE, A2, B2, m0, n0,
                         j * BK, t);
    }

    // Epilogue: c-frag lane mapping: c0,c1 -> (row L/4, col 2(L%4)); c2,c3 -> row+8
    const int er = lane >> 2;
    const int ec = (lane & 3) << 1;
#pragma unroll
    for (int mi = 0; mi < 4; ++mi) {
#pragma unroll
        for (int nj = 0; nj < 4; ++nj) {
            size_t r0 = (size_t)(m0 + wm + mi * 16 + er) * HDIM
                        + (n0 + wn + nj * 8 + ec);
            *(float2*)&C[r0]              = make_float2(acc[mi][nj][0], acc[mi][nj][1]);
            *(float2*)&C[r0 + 8 * HDIM]   = make_float2(acc[mi][nj][2], acc[mi][nj][3]);
        }
    }
}

// ===========================================================================
// RoPE in-place on Q and K (validated)
// ===========================================================================
__global__ void rope_kernel(float* __restrict__ Q, float* __restrict__ K,
                            const int* __restrict__ pos)
{
    int idx = blockIdx.x * 256 + threadIdx.x;
    const int total = S_LEN * NHEADS * 64;
    if (idx >= total) return;
    int j = idx & 63;
    int h = (idx >> 6) & (NHEADS - 1);
    int s = idx >> 11;

    int p = pos[s];
    float inv = 1.0f / powf(10000.0f, (float)j * (1.0f / 64.0f));
    float ang = (float)p * inv;
    float sn, cs;
    sincosf(ang, &sn, &cs);

    size_t base = (size_t)s * HDIM + (size_t)h * HEADD + j;
    float q1 = Q[base], q2 = Q[base + 64];
    Q[base]      = q1 * cs - q2 * sn;
    Q[base + 64] = q2 * cs + q1 * sn;
    float k1 = K[base], k2 = K[base + 64];
    K[base]      = k1 * cs - k2 * sn;
    K[base + 64] = k2 * cs + k1 * sn;
}

// ===========================================================================
// Flash attention (causal), fp32 (validated)
// ===========================================================================
#define NEG_BIG (-3.0e38f)
#define FLASH_SMEM ((128 * 68 * 2 + 64 * 68 + 192) * 4)

__global__ void __launch_bounds__(256) flash_attn(const float* __restrict__ Q,
                                                  const float* __restrict__ K,
                                                  const float* __restrict__ V,
                                                  float* __restrict__ O)
{
    extern __shared__ float sm[];
    float* Qts  = sm;
    float* KV   = Qts + 128 * 68;
    float* Ss   = KV + 128 * 68;
    float* mrow = Ss + 64 * 68;
    float* lrow = mrow + 64;
    float* srow = lrow + 64;

    const int qb = blockIdx.x;
    const int h  = blockIdx.y;
    const int q0 = qb * 64;
    const int t  = threadIdx.x;
    const int tx = t & 15;
    const int ty = t >> 4;
    const float scale = 0.08838834764831843f;

    for (int i = t; i < 64 * 32; i += 256) {
        int r  = i >> 5;
        int c4 = (i & 31) << 2;
        float4 v = *(const float4*)&Q[(size_t)(q0 + r) * HDIM + (size_t)h * HEADD + c4];
        Qts[(c4 + 0) * 68 + r] = v.x * scale;
        Qts[(c4 + 1) * 68 + r] = v.y * scale;
        Qts[(c4 + 2) * 68 + r] = v.z * scale;
        Qts[(c4 + 3) * 68 + r] = v.w * scale;
    }
    if (t < 64) { mrow[t] = NEG_BIG; lrow[t] = 0.0f; }

    float o[4][8];
#pragma unroll
    for (int i = 0; i < 4; ++i)
#pragma unroll
        for (int j = 0; j < 8; ++j) o[i][j] = 0.0f;

    for (int kb = 0; kb <= qb; ++kb) {
        const int k0 = kb * 64;
        __syncthreads();

        for (int i = t; i < 64 * 32; i += 256) {
            int r  = i >> 5;
            int c4 = (i & 31) << 2;
            float4 v = *(const float4*)&K[(size_t)(k0 + r) * HDIM + (size_t)h * HEADD + c4];
            KV[(c4 + 0) * 68 + r] = v.x;
            KV[(c4 + 1) * 68 + r] = v.y;
            KV[(c4 + 2) * 68 + r] = v.z;
            KV[(c4 + 3) * 68 + r] = v.w;
        }
        __syncthreads();

        float sacc[4][4];
#pragma unroll
        for (int i = 0; i < 4; ++i)
#pragma unroll
            for (int j = 0; j < 4; ++j) sacc[i][j] = 0.0f;

#pragma unroll 4
        for (int d = 0; d < 128; ++d) {
            float4 qv = *(const float4*)&Qts[d * 68 + (ty << 2)];
            float4 kv = *(const float4*)&KV[d * 68 + (tx << 2)];
            float qa[4] = {qv.x, qv.y, qv.z, qv.w};
            float ka[4] = {kv.x, kv.y, kv.z, kv.w};
#pragma unroll
            for (int i = 0; i < 4; ++i)
#pragma unroll
                for (int j = 0; j < 4; ++j)
                    sacc[i][j] = fmaf(qa[i], ka[j], sacc[i][j]);
        }

        const bool diag = (kb == qb);
#pragma unroll
        for (int i = 0; i < 4; ++i) {
            int rg = ty * 4 + i;
#pragma unroll
            for (int j = 0; j < 4; ++j) {
                int cg = tx * 4 + j;
                float v = sacc[i][j];
                if (diag && cg > rg) v = NEG_BIG;
                Ss[rg * 68 + cg] = v;
            }
        }
        __syncthreads();

        {
            int r  = t >> 2;
            int qd = t & 3;
            float* srw = &Ss[r * 68 + qd * 16];
            float vals[16];
            float mx = NEG_BIG;
#pragma unroll
            for (int i = 0; i < 16; ++i) { vals[i] = srw[i]; mx = fmaxf(mx, vals[i]); }
            mx = fmaxf(mx, __shfl_xor_sync(0xffffffffu, mx, 1));
            mx = fmaxf(mx, __shfl_xor_sync(0xffffffffu, mx, 2));
            float mold = mrow[r];
            float mnew = fmaxf(mold, mx);
            float sum = 0.0f;
#pragma unroll
            for (int i = 0; i < 16; ++i) {
                float p = __expf(vals[i] - mnew);
                srw[i] = p;
                sum += p;
            }
            sum += __shfl_xor_sync(0xffffffffu, sum, 1);
            sum += __shfl_xor_sync(0xffffffffu, sum, 2);
            float corr = __expf(mold - mnew);
            if (qd == 0) {
                mrow[r] = mnew;
                lrow[r] = lrow[r] * corr + sum;
                srow[r] = corr;
            }
        }

        for (int i = t; i < 64 * 32; i += 256) {
            int r  = i >> 5;
            int c4 = (i & 31) << 2;
            *(float4*)&KV[r * 132 + c4] =
                *(const float4*)&V[(size_t)(k0 + r) * HDIM + (size_t)h * HEADD + c4];
        }
        __syncthreads();

        float corr[4];
#pragma unroll
        for (int i = 0; i < 4; ++i) corr[i] = srow[ty * 4 + i];
#pragma unroll
        for (int i = 0; i < 4; ++i)
#pragma unroll
            for (int j = 0; j < 8; ++j) o[i][j] *= corr[i];

#pragma unroll 2
        for (int kk = 0; kk < 64; ++kk) {
            float4 va = *(const float4*)&KV[kk * 132 + (tx << 3)];
            float4 vb = *(const float4*)&KV[kk * 132 + (tx << 3) + 4];
            float vv[8] = {va.x, va.y, va.z, va.w, vb.x, vb.y, vb.z, vb.w};
            float pr[4];
#pragma unroll
            for (int i = 0; i < 4; ++i) pr[i] = Ss[(ty * 4 + i) * 68 + kk];
#pragma unroll
            for (int i = 0; i < 4; ++i)
#pragma unroll
                for (int j = 0; j < 8; ++j)
                    o[i][j] = fmaf(pr[i], vv[j], o[i][j]);
        }
    }

    float linv[4];
#pragma unroll
    for (int i = 0; i < 4; ++i) linv[i] = 1.0f / lrow[ty * 4 + i];
#pragma unroll
    for (int i = 0; i < 4; ++i) {
        size_t base = (size_t)(q0 + ty * 4 + i) * HDIM + (size_t)h * HEADD + (tx << 3);
        float4 r0 = make_float4(o[i][0] * linv[i], o[i][1] * linv[i],
                                o[i][2] * linv[i], o[i][3] * linv[i]);
        float4 r1 = make_float4(o[i][4] * linv[i], o[i][5] * linv[i],
                                o[i][6] * linv[i], o[i][7] * linv[i]);
        *(float4*)&O[base]     = r0;
        *(float4*)&O[base + 4] = r1;
    }
}

// ===========================================================================
// Launch
// ===========================================================================
extern "C" void kernel_launch(void* const* d_in, const int* in_sizes, int n_in,
                              void* d_out, int out_size)
{
    (void)in_sizes; (void)n_in; (void)out_size;

    const float* X   = (const float*)d_in[0];
    const int*   pos = (const int*)d_in[2];
    const float* Wq  = (const float*)d_in[3];
    const float* Wk  = (const float*)d_in[4];
    const float* Wv  = (const float*)d_in[5];
    const float* Wo  = (const float*)d_in[6];
    float* out = (float*)d_out;

    float *Qd, *Kd, *Vd, *Ad;
    __nv_bfloat16 *A2d, *W2qd, *W2kd, *W2vd, *W2od;
    cudaGetSymbolAddress((void**)&Qd, g_Q);
    cudaGetSymbolAddress((void**)&Kd, g_K);
    cudaGetSymbolAddress((void**)&Vd, g_V);
    cudaGetSymbolAddress((void**)&Ad, g_A);
    cudaGetSymbolAddress((void**)&A2d, g_A2);
    cudaGetSymbolAddress((void**)&W2qd, g_W2q);
    cudaGetSymbolAddress((void**)&W2kd, g_W2k);
    cudaGetSymbolAddress((void**)&W2vd, g_W2v);
    cudaGetSymbolAddress((void**)&W2od, g_W2o);

    cudaFuncSetAttribute(flash_attn, cudaFuncAttributeMaxDynamicSharedMemorySize,
                         FLASH_SMEM);
    cudaFuncSetAttribute(gemm_mma, cudaFuncAttributeMaxDynamicSharedMemorySize,
                         GSMEM);

    // Splits: activations [hi|hi|lo], weights [hi|lo|hi]
    split_bf16<<<(S_LEN * 1024) / 256, 256>>>(X, A2d, S_LEN * 1024);
    split_bf16_w<<<(HDIM * 1024) / 256, 256>>>(Wq, W2qd, HDIM * 1024);
    split_bf16_w<<<(HDIM * 1024) / 256, 256>>>(Wk, W2kd, HDIM * 1024);
    split_bf16_w<<<(HDIM * 1024) / 256, 256>>>(Wv, W2vd, HDIM * 1024);
    split_bf16_w<<<(HDIM * 1024) / 256, 256>>>(Wo, W2od, HDIM * 1024);

    dim3 ggrid(HDIM / BN, S_LEN / BM);   // (32, 16)

    gemm_mma<<<ggrid, 256, GSMEM>>>(A2d, W2qd, Qd);
    gemm_mma<<<ggrid, 256, GSMEM>>>(A2d, W2kd, Kd);
    gemm_mma<<<ggrid, 256, GSMEM>>>(A2d, W2vd, Vd);

    {
        int total = S_LEN * NHEADS * 64;
        rope_kernel<<<(total + 255) / 256, 256>>>(Qd, Kd, pos);
    }

    flash_attn<<<dim3(S_LEN / 64, NHEADS), 256, FLASH_SMEM>>>(Qd, Kd, Vd, Ad);

    split_bf16<<<(S_LEN * 1024) / 256, 256>>>(Ad, A2d, S_LEN * 1024);
    gemm_mma<<<ggrid, 256, GSMEM>>>(A2d, W2od, out);
}

// round 7
// speedup vs baseline: 2.8620x; 1.3841x over previous
#include <cuda_runtime.h>
#include <cuda_bf16.h>
#include <math.h>
#include <stdint.h>

// Problem constants
#define S_LEN  2048
#define HDIM   4096     // hidden = NH*HD
#define NHEADS 32
#define HEADD  128
#define HD2    256      // head-dim split storage: [hi(128) | lo(128)]

#define K2     12288    // 3 * HDIM (bf16x2 split for projections)

// Scratch (device globals: allocation-free rule)
__device__ float g_Q[S_LEN * HDIM];
__device__ float g_K[S_LEN * HDIM];
__device__ float g_V[S_LEN * HDIM];
__device__ float g_A[S_LEN * HDIM];
__device__ __nv_bfloat16 g_A2[S_LEN * K2];
__device__ __nv_bfloat16 g_W2q[HDIM * K2];
__device__ __nv_bfloat16 g_W2k[HDIM * K2];
__device__ __nv_bfloat16 g_W2v[HDIM * K2];
__device__ __nv_bfloat16 g_W2o[HDIM * K2];
__device__ __nv_bfloat16 g_Q2[NHEADS * S_LEN * HD2];   // [h][s][Qh|Ql]
__device__ __nv_bfloat16 g_K2a[NHEADS * S_LEN * HD2];  // [h][s][Kh|Kl]
__device__ __nv_bfloat16 g_Vb[NHEADS * S_LEN * HD2];   // [h][s][Vh|Vl]

// ===========================================================================
// PTX helpers (base PTX only)
// ===========================================================================
__device__ __forceinline__ uint32_t smem_u32(const void* p) {
    uint32_t a;
    asm("{ .reg .u64 t; cvta.to.shared.u64 t, %1; cvt.u32.u64 %0, t; }" : "=r"(a) : "l"(p));
    return a;
}
__device__ __forceinline__ void cp_async16(uint32_t dst, const void* src) {
    asm volatile("cp.async.cg.shared.global [%0], [%1], 16;" :: "r"(dst), "l"(src));
}
__device__ __forceinline__ void cp_commit() {
    asm volatile("cp.async.commit_group;" ::: "memory");
}
template <int N> __device__ __forceinline__ void cp_wait() {
    asm volatile("cp.async.wait_group %0;" :: "n"(N) : "memory");
}
__device__ __forceinline__ void ldsm_x4(uint32_t& r0, uint32_t& r1, uint32_t& r2,
                                        uint32_t& r3, uint32_t addr) {
    asm volatile("ldmatrix.sync.aligned.m8n8.x4.shared.b16 {%0,%1,%2,%3}, [%4];"
                 : "=r"(r0), "=r"(r1), "=r"(r2), "=r"(r3) : "r"(addr));
}
__device__ __forceinline__ void ldsm_x4t(uint32_t& r0, uint32_t& r1, uint32_t& r2,
                                         uint32_t& r3, uint32_t addr) {
    asm volatile("ldmatrix.sync.aligned.m8n8.x4.trans.shared.b16 {%0,%1,%2,%3}, [%4];"
                 : "=r"(r0), "=r"(r1), "=r"(r2), "=r"(r3) : "r"(addr));
}
__device__ __forceinline__ void mma16816(float* c, const uint32_t* a, const uint32_t* b) {
    asm volatile(
        "mma.sync.aligned.m16n8k16.row.col.f32.bf16.bf16.f32 "
        "{%0,%1,%2,%3}, {%4,%5,%6,%7}, {%8,%9}, {%0,%1,%2,%3};"
        : "+f"(c[0]), "+f"(c[1]), "+f"(c[2]), "+f"(c[3])
        : "r"(a[0]), "r"(a[1]), "r"(a[2]), "r"(a[3]), "r"(b[0]), "r"(b[1]));
}

__device__ __forceinline__ uint32_t pkb(__nv_bfloat16 a, __nv_bfloat16 b) {
    __nv_bfloat162 t = __halves2bfloat162(a, b);
    return *reinterpret_cast<uint32_t*>(&t);
}
__device__ __forceinline__ void split2(float x, __nv_bfloat16& h, __nv_bfloat16& l) {
    h = __float2bfloat16_rn(x);
    l = __float2bfloat16_rn(x - __bfloat162float(h));
}

// ===========================================================================
// fp32 -> bf16x2 split kernels (projections)
// ===========================================================================
__global__ void __launch_bounds__(256) split_bf16(const float* __restrict__ src,
                                                  __nv_bfloat16* __restrict__ dst,
                                                  int total4)
{
    int i = blockIdx.x * 256 + threadIdx.x;
    if (i >= total4) return;
    int row = i >> 10;
    int c4  = (i & 1023) << 2;
    float4 v = ((const float4*)src)[i];
    float in[4] = {v.x, v.y, v.z, v.w};
    __nv_bfloat16 h[4], l[4];
#pragma unroll
    for (int j = 0; j < 4; ++j) split2(in[j], h[j], l[j]);
    uint2 hh = make_uint2(pkb(h[0], h[1]), pkb(h[2], h[3]));
    uint2 ll = make_uint2(pkb(l[0], l[1]), pkb(l[2], l[3]));
    size_t b = (size_t)row * K2 + c4;
    *(uint2*)(dst + b)            = hh;
    *(uint2*)(dst + b + HDIM)     = hh;
    *(uint2*)(dst + b + 2 * HDIM) = ll;
}

__global__ void __launch_bounds__(256) split_bf16_w(const float* __restrict__ src,
                                                    __nv_bfloat16* __restrict__ dst,
                                                    int total4)
{
    int i = blockIdx.x * 256 + threadIdx.x;
    if (i >= total4) return;
    int row = i >> 10;
    int c4  = (i & 1023) << 2;
    float4 v = ((const float4*)src)[i];
    float in[4] = {v.x, v.y, v.z, v.w};
    __nv_bfloat16 h[4], l[4];
#pragma unroll
    for (int j = 0; j < 4; ++j) split2(in[j], h[j], l[j]);
    uint2 hh = make_uint2(pkb(h[0], h[1]), pkb(h[2], h[3]));
    uint2 ll = make_uint2(pkb(l[0], l[1]), pkb(l[2], l[3]));
    size_t b = (size_t)row * K2 + c4;
    *(uint2*)(dst + b)            = hh;
    *(uint2*)(dst + b + HDIM)     = ll;
    *(uint2*)(dst + b + 2 * HDIM) = hh;
}

// ===========================================================================
// mma.sync bf16 GEMM (validated R5): C[2048,4096] = A2 @ B2^T, fp32 out
// ===========================================================================
#define BM 128
#define BN 128
#define BK 32
#define NITER   (K2 / BK)
#define GSTAGES 4
#define ROWB    80
#define ASZ     (BM * ROWB)
#define STAGE   (2 * ASZ)
#define GSMEM   (GSTAGES * STAGE)

__device__ __forceinline__ void g_load_stage(uint32_t sb,
                                             const __nv_bfloat16* __restrict__ A2,
                                             const __nv_bfloat16* __restrict__ B2,
                                             int m0, int n0, int k0, int t)
{
#pragma unroll
    for (int i = 0; i < 2; ++i) {
        int c   = t + (i << 8);
        int row = c >> 2;
        int kc  = c & 3;
        cp_async16(sb + row * ROWB + kc * 16,
                   A2 + (size_t)(m0 + row) * K2 + k0 + kc * 8);
    }
#pragma unroll
    for (int i = 0; i < 2; ++i) {
        int c   = t + (i << 8);
        int row = c >> 2;
        int kc  = c & 3;
        cp_async16(sb + ASZ + row * ROWB + kc * 16,
                   B2 + (size_t)(n0 + row) * K2 + k0 + kc * 8);
    }
    cp_commit();
}

__global__ void __launch_bounds__(256)
gemm_mma(const __nv_bfloat16* __restrict__ A2,
         const __nv_bfloat16* __restrict__ B2,
         float* __restrict__ C)
{
    extern __shared__ char smraw[];
    const uint32_t base = smem_u32(smraw);
    const int t    = threadIdx.x;
    const int wid  = t >> 5;
    const int lane = t & 31;
    const int m0   = blockIdx.y * BM;
    const int n0   = blockIdx.x * BN;
    const int wm   = (wid >> 2) * 64;
    const int wn   = (wid & 3) * 32;

    const int rA   = lane & 15;
    const int selA = lane >> 4;
    const int rB   = ((lane >> 4) << 3) | (lane & 7);
    const int selB = (lane >> 3) & 1;

    float acc[4][4][4];
#pragma unroll
    for (int mi = 0; mi < 4; ++mi)
#pragma unroll
        for (int nj = 0; nj < 4; ++nj)
#pragma unroll
            for (int q = 0; q < 4; ++q) acc[mi][nj][q] = 0.0f;

#pragma unroll
    for (int it = 0; it < GSTAGES - 1; ++it)
        g_load_stage(base + it * STAGE, A2, B2, m0, n0, it * BK, t);

    for (int it = 0; it < NITER; ++it) {
        const int st = it & (GSTAGES - 1);
        cp_wait<GSTAGES - 2>();
        __syncthreads();

        const uint32_t stA = base + st * STAGE;
        const uint32_t stB = stA + ASZ;

#pragma unroll
        for (int kh = 0; kh < 2; ++kh) {
            uint32_t a[4][4];
#pragma unroll
            for (int mi = 0; mi < 4; ++mi)
                ldsm_x4(a[mi][0], a[mi][1], a[mi][2], a[mi][3],
                        stA + (uint32_t)((wm + mi * 16 + rA) * ROWB
                                         + (kh * 2 + selA) * 16));
            uint32_t b[2][4];
#pragma unroll
            for (int p = 0; p < 2; ++p)
                ldsm_x4(b[p][0], b[p][1], b[p][2], b[p][3],
                        stB + (uint32_t)((wn + p * 16 + rB) * ROWB
                                         + (kh * 2 + selB) * 16));
#pragma unroll
            for (int mi = 0; mi < 4; ++mi) {
#pragma unroll
                for (int nj = 0; nj < 4; ++nj) {
                    const uint32_t* bf = &b[nj >> 1][(nj & 1) << 1];
                    mma16816(acc[mi][nj], a[mi], bf);
                }
            }
        }

        const int j = it + GSTAGES - 1;
        if (j < NITER)
            g_load_stage(base + (j & (GSTAGES - 1)) * STAGE, A2, B2, m0, n0,
                         j * BK, t);
    }

    const int er = lane >> 2;
    const int ec = (lane & 3) << 1;
#pragma unroll
    for (int mi = 0; mi < 4; ++mi) {
#pragma unroll
        for (int nj = 0; nj < 4; ++nj) {
            size_t r0 = (size_t)(m0 + wm + mi * 16 + er) * HDIM
                        + (n0 + wn + nj * 8 + ec);
            *(float2*)&C[r0]            = make_float2(acc[mi][nj][0], acc[mi][nj][1]);
            *(float2*)&C[r0 + 8 * HDIM] = make_float2(acc[mi][nj][2], acc[mi][nj][3]);
        }
    }
}

// ===========================================================================
// Fused RoPE + head-dim split: Q2[h][s][256]=[Qh|Ql]*scale, K2=[Kh|Kl]
// ===========================================================================
#define ATT_SCALE 0.08838834764831843f   // 1/sqrt(128)

__global__ void __launch_bounds__(256) rope_split_qk(
    const float* __restrict__ Q, const float* __restrict__ K,
    const int* __restrict__ pos,
    __nv_bfloat16* __restrict__ Q2, __nv_bfloat16* __restrict__ K2o)
{
    int idx = blockIdx.x * 256 + threadIdx.x;        // S*NH*16
    if (idx >= S_LEN * NHEADS * 16) return;
    int j4 = (idx & 15) << 2;                         // 0..60
    int h  = (idx >> 4) & (NHEADS - 1);
    int s  = idx >> 9;
    int p  = pos[s];

    float sn[4], cs[4];
#pragma unroll
    for (int i = 0; i < 4; ++i) {
        float inv = 1.0f / powf(10000.0f, (float)(j4 + i) * (1.0f / 64.0f));
        sincosf((float)p * inv, &sn[i], &cs[i]);
    }

    size_t gb = (size_t)s * HDIM + (size_t)h * HEADD + j4;
    float4 qa4 = *(const float4*)&Q[gb];
    float4 qb4 = *(const float4*)&Q[gb + 64];
    float4 ka4 = *(const float4*)&K[gb];
    float4 kb4 = *(const float4*)&K[gb + 64];
    float qa[4] = {qa4.x, qa4.y, qa4.z, qa4.w};
    float qb[4] = {qb4.x, qb4.y, qb4.z, qb4.w};
    float ka[4] = {ka4.x, ka4.y, ka4.z, ka4.w};
    float kb[4] = {kb4.x, kb4.y, kb4.z, kb4.w};

    __nv_bfloat16 qah[4], qal[4], qbh[4], qbl[4];
    __nv_bfloat16 kah[4], kal[4], kbh[4], kbl[4];
#pragma unroll
    for (int i = 0; i < 4; ++i) {
        float r1 = (qa[i] * cs[i] - qb[i] * sn[i]) * ATT_SCALE;
        float r2 = (qb[i] * cs[i] + qa[i] * sn[i]) * ATT_SCALE;
        split2(r1, qah[i], qal[i]);
        split2(r2, qbh[i], qbl[i]);
        float t1 = ka[i] * cs[i] - kb[i] * sn[i];
        float t2 = kb[i] * cs[i] + ka[i] * sn[i];
        split2(t1, kah[i], kal[i]);
        split2(t2, kbh[i], kbl[i]);
    }

    size_t ob = ((size_t)h * S_LEN + s) * HD2 + j4;
    // [hi(0..127) | lo(128..255)]
    *(uint2*)(Q2 + ob)       = make_uint2(pkb(qah[0], qah[1]), pkb(qah[2], qah[3]));
    *(uint2*)(Q2 + ob + 64)  = make_uint2(pkb(qbh[0], qbh[1]), pkb(qbh[2], qbh[3]));
    *(uint2*)(Q2 + ob + 128) = make_uint2(pkb(qal[0], qal[1]), pkb(qal[2], qal[3]));
    *(uint2*)(Q2 + ob + 192) = make_uint2(pkb(qbl[0], qbl[1]), pkb(qbl[2], qbl[3]));

    *(uint2*)(K2o + ob)       = make_uint2(pkb(kah[0], kah[1]), pkb(kah[2], kah[3]));
    *(uint2*)(K2o + ob + 64)  = make_uint2(pkb(kbh[0], kbh[1]), pkb(kbh[2], kbh[3]));
    *(uint2*)(K2o + ob + 128) = make_uint2(pkb(kal[0], kal[1]), pkb(kal[2], kal[3]));
    *(uint2*)(K2o + ob + 192) = make_uint2(pkb(kbl[0], kbl[1]), pkb(kbl[2], kbl[3]));
}

// V fp32 [s][4096] -> split bf16 [h][s][Vh(128)|Vl(128)]
__global__ void __launch_bounds__(256) conv_v(const float* __restrict__ V,
                                              __nv_bfloat16* __restrict__ Vb)
{
    int i = blockIdx.x * 256 + threadIdx.x;   // S*1024
    if (i >= S_LEN * 1024) return;
    int s  = i >> 10;
    int hc = i & 1023;
    int h  = hc >> 5;
    int c4 = (hc & 31) << 2;
    float4 v = ((const float4*)V)[i];
    float in[4] = {v.x, v.y, v.z, v.w};
    __nv_bfloat16 hh[4], ll[4];
#pragma unroll
    for (int j = 0; j < 4; ++j) split2(in[j], hh[j], ll[j]);
    size_t ob = ((size_t)h * S_LEN + s) * HD2 + c4;
    *(uint2*)(Vb + ob)       = make_uint2(pkb(hh[0], hh[1]), pkb(hh[2], hh[3]));
    *(uint2*)(Vb + ob + 128) = make_uint2(pkb(ll[0], ll[1]), pkb(ll[2], ll[3]));
}

// ===========================================================================
// Flash attention v3 (tensor cores, fully split): 64 q-rows per CTA, causal.
// Scores = QhKh + QhKl + QlKh (3 passes over [hi|lo] tiles).
// Softmax fp32 -> emits Ph and Pl.  PV = PhVh + PhVl + PlVh (3 passes).
// K/V double-buffered via cp.async.
// ===========================================================================
#define NEG_BIG (-3.0e38f)
#define FROW2  528    // 256 bf16 = 512B + 16 pad (33x16B, odd -> conflict-free)
#define FROWP  272    // 128 bf16 = 256B + 16 pad
#define OFF_K2S  (64 * FROW2)                         // 33792
#define OFF_VS   (OFF_K2S + 2 * 64 * FROW2)           // 101376
#define OFF_SS   (OFF_VS + 2 * 64 * FROW2)            // 168960
#define OFF_PS   (OFF_SS + 64 * 68 * 4)               // 186368
#define OFF_RW   (OFF_PS + 64 * FROWP)                // 203776
#define FSMEM    (OFF_RW + 3 * 64 * 4)                // 204544

__device__ __forceinline__ void f_load_kv(uint32_t sb, int buf,
                                          const __nv_bfloat16* __restrict__ K2g,
                                          const __nv_bfloat16* __restrict__ Vg,
                                          int t)
{
    uint32_t kb = sb + OFF_K2S + buf * (64 * FROW2);
    for (int c = t; c < 64 * 32; c += 256) {
        int r = c >> 5, ch = c & 31;
        cp_async16(kb + r * FROW2 + ch * 16,
                   (const char*)K2g + (size_t)r * (HD2 * 2) + ch * 16);
    }
    uint32_t vb = sb + OFF_VS + buf * (64 * FROW2);
    for (int c = t; c < 64 * 32; c += 256) {
        int r = c >> 5, ch = c & 31;
        cp_async16(vb + r * FROW2 + ch * 16,
                   (const char*)Vg + (size_t)r * (HD2 * 2) + ch * 16);
    }
    cp_commit();
}

__global__ void __launch_bounds__(256) flash2(
    const __nv_bfloat16* __restrict__ Q2,
    const __nv_bfloat16* __restrict__ K2g,
    const __nv_bfloat16* __restrict__ Vb,
    float* __restrict__ O)
{
    extern __shared__ char smraw[];
    const uint32_t sb = smem_u32(smraw);
    float* Ss  = (float*)(smraw + OFF_SS);
    __nv_bfloat16* Ps = (__nv_bfloat16*)(smraw + OFF_PS);
    float* mrow = (float*)(smraw + OFF_RW);
    float* lrow = mrow + 64;
    float* srow = lrow + 64;

    const int h  = blockIdx.x;
    const int qb = (gridDim.y - 1) - blockIdx.y;   // heavy blocks first
    const int q0 = qb * 64;
    const int t = threadIdx.x, wid = t >> 5, lane = t & 31;
    const int wm = (wid >> 2) * 32;     // q-rows: 2 warp groups of 32
    const int wn = (wid & 3) * 16;      // score cols: 4 x 16
    const int wnv = (wid & 3) * 32;     // PV cols: 4 x 32
    const int rA = lane & 15, selA = lane >> 4;
    const int rB = ((lane >> 4) << 3) | (lane & 7), selB = (lane >> 3) & 1;
    const int er = lane >> 2, ec = (lane & 3) << 1;

    // Q tile load (once): 64 rows x 512B
    const __nv_bfloat16* Qg = Q2 + ((size_t)h * S_LEN + q0) * HD2;
    for (int c = t; c < 64 * 32; c += 256) {
        int r = c >> 5, ch = c & 31;
        cp_async16(sb + r * FROW2 + ch * 16,
                   (const char*)Qg + (size_t)r * (HD2 * 2) + ch * 16);
    }
    cp_commit();
    if (t < 64) { mrow[t] = NEG_BIG; lrow[t] = 0.0f; }

    f_load_kv(sb, 0, K2g + ((size_t)h * S_LEN) * HD2,
              Vb + ((size_t)h * S_LEN) * HD2, t);

    float oacc[2][4][4];
#pragma unroll
    for (int mi = 0; mi < 2; ++mi)
#pragma unroll
        for (int nj = 0; nj < 4; ++nj)
#pragma unroll
            for (int q = 0; q < 4; ++q) oacc[mi][nj][q] = 0.0f;

    for (int kb = 0; kb <= qb; ++kb) {
        const int buf = kb & 1;
        cp_wait<0>();
        __syncthreads();

        if (kb + 1 <= qb)
            f_load_kv(sb, buf ^ 1,
                      K2g + ((size_t)h * S_LEN + (kb + 1) * 64) * HD2,
                      Vb + ((size_t)h * S_LEN + (kb + 1) * 64) * HD2, t);

        const uint32_t kbase = sb + OFF_K2S + buf * (64 * FROW2);
        const uint32_t vbase = sb + OFF_VS + buf * (64 * FROW2);

        // ---- scores: 3 passes (Qh,Kh),(Qh,Kl),(Ql,Kh); each K=128 ----
        float sacc[2][2][4];
#pragma unroll
        for (int mi = 0; mi < 2; ++mi)
#pragma unroll
            for (int nj = 0; nj < 2; ++nj)
#pragma unroll
                for (int q = 0; q < 4; ++q) sacc[mi][nj][q] = 0.0f;

        const uint32_t sAoff[3] = {0u, 0u, 256u};   // Q seg byte offset
        const uint32_t sBoff[3] = {0u, 256u, 0u};   // K seg byte offset
#pragma unroll
        for (int ps = 0; ps < 3; ++ps) {
#pragma unroll
            for (int k16 = 0; k16 < 8; ++k16) {
                uint32_t a[2][4], b[4];
#pragma unroll
                for (int mi = 0; mi < 2; ++mi)
                    ldsm_x4(a[mi][0], a[mi][1], a[mi][2], a[mi][3],
                            sb + (uint32_t)((wm + mi * 16 + rA) * FROW2)
                               + sAoff[ps] + k16 * 32 + selA * 16);
                ldsm_x4(b[0], b[1], b[2], b[3],
                        kbase + (uint32_t)((wn + rB) * FROW2)
                              + sBoff[ps] + k16 * 32 + selB * 16);
#pragma unroll
                for (int mi = 0; mi < 2; ++mi)
#pragma unroll
                    for (int nj = 0; nj < 2; ++nj)
                        mma16816(sacc[mi][nj], a[mi], &b[nj << 1]);
            }
        }

        const bool diag = (kb == qb);
#pragma unroll
        for (int mi = 0; mi < 2; ++mi) {
#pragma unroll
            for (int nj = 0; nj < 2; ++nj) {
                int row = wm + mi * 16 + er;
                int col = wn + nj * 8 + ec;
                float v0 = sacc[mi][nj][0], v1 = sacc[mi][nj][1];
                float v2 = sacc[mi][nj][2], v3 = sacc[mi][nj][3];
                if (diag) {
                    if (col > row)     v0 = NEG_BIG;
                    if (col + 1 > row) v1 = NEG_BIG;
                    if (col > row + 8)     v2 = NEG_BIG;
                    if (col + 1 > row + 8) v3 = NEG_BIG;
                }
                Ss[row * 68 + col]       = v0;
                Ss[row * 68 + col + 1]   = v1;
                Ss[(row + 8) * 68 + col]     = v2;
                Ss[(row + 8) * 68 + col + 1] = v3;
            }
        }
        __syncthreads();

        // ---- online softmax: emits Ph (cols 0-63) and Pl (cols 64-127) ----
        {
            int r  = t >> 2;
            int qd = t & 3;
            float* srw = &Ss[r * 68 + qd * 16];
            __nv_bfloat16* prw = &Ps[r * 136 + qd * 16];
            float vals[16];
            float mx = NEG_BIG;
#pragma unroll
            for (int i = 0; i < 16; ++i) { vals[i] = srw[i]; mx = fmaxf(mx, vals[i]); }
            mx = fmaxf(mx, __shfl_xor_sync(0xffffffffu, mx, 1));
            mx = fmaxf(mx, __shfl_xor_sync(0xffffffffu, mx, 2));
            float mold = mrow[r];
            float mnew = fmaxf(mold, mx);
            float sum = 0.0f;
#pragma unroll
            for (int i = 0; i < 16; ++i) {
                float p = __expf(vals[i] - mnew);
                __nv_bfloat16 ph, pl;
                split2(p, ph, pl);
                prw[i]      = ph;
                prw[i + 64] = pl;
                sum += p;
            }
            sum += __shfl_xor_sync(0xffffffffu, sum, 1);
            sum += __shfl_xor_sync(0xffffffffu, sum, 2);
            float corr = __expf(mold - mnew);
            if (qd == 0) {
                mrow[r] = mnew;
                lrow[r] = lrow[r] * corr + sum;
                srow[r] = corr;
            }
        }
        __syncthreads();

        // ---- rescale + PV: 3 passes (Ph,Vh),(Ph,Vl),(Pl,Vh) ----
#pragma unroll
        for (int mi = 0; mi < 2; ++mi) {
            float c0 = srow[wm + mi * 16 + er];
            float c1 = srow[wm + mi * 16 + er + 8];
#pragma unroll
            for (int nj = 0; nj < 4; ++nj) {
                oacc[mi][nj][0] *= c0; oacc[mi][nj][1] *= c0;
                oacc[mi][nj][2] *= c1; oacc[mi][nj][3] *= c1;
            }
        }

        const int vkr = ((lane >> 3) & 1) * 8 + (lane & 7);
        const int vnc = (lane >> 4) * 8;
        const uint32_t pAoff[3] = {0u, 0u, 128u};    // P seg byte offset
        const uint32_t pVoff[3] = {0u, 256u, 0u};    // V seg byte offset
#pragma unroll
        for (int ps = 0; ps < 3; ++ps) {
#pragma unroll
            for (int kk = 0; kk < 4; ++kk) {
                uint32_t a[2][4], b0[4], b1[4];
#pragma unroll
                for (int mi = 0; mi < 2; ++mi)
                    ldsm_x4(a[mi][0], a[mi][1], a[mi][2], a[mi][3],
                            sb + OFF_PS + (uint32_t)((wm + mi * 16 + rA) * FROWP)
                               + pAoff[ps] + kk * 32 + selA * 16);
                uint32_t vaddr = vbase + (uint32_t)((kk * 16 + vkr) * FROW2)
                               + pVoff[ps];
                ldsm_x4t(b0[0], b0[1], b0[2], b0[3], vaddr + (wnv + vnc) * 2);
                ldsm_x4t(b1[0], b1[1], b1[2], b1[3], vaddr + (wnv + 16 + vnc) * 2);
#pragma unroll
                for (int mi = 0; mi < 2; ++mi) {
                    mma16816(oacc[mi][0], a[mi], &b0[0]);
                    mma16816(oacc[mi][1], a[mi], &b0[2]);
                    mma16816(oacc[mi][2], a[mi], &b1[0]);
                    mma16816(oacc[mi][3], a[mi], &b1[2]);
                }
            }
        }
    }

    // epilogue: normalize, store fp32 to O [s][4096]
#pragma unroll
    for (int mi = 0; mi < 2; ++mi) {
        float l0 = 1.0f / lrow[wm + mi * 16 + er];
        float l1 = 1.0f / lrow[wm + mi * 16 + er + 8];
#pragma unroll
        for (int nj = 0; nj < 4; ++nj) {
            size_t r0 = (size_t)(q0 + wm + mi * 16 + er) * HDIM
                        + (size_t)h * HEADD + wnv + nj * 8 + ec;
            *(float2*)&O[r0]            = make_float2(oacc[mi][nj][0] * l0,
                                                      oacc[mi][nj][1] * l0);
            *(float2*)&O[r0 + 8 * HDIM] = make_float2(oacc[mi][nj][2] * l1,
                                                      oacc[mi][nj][3] * l1);
        }
    }
}

// ===========================================================================
// Launch
// ===========================================================================
extern "C" void kernel_launch(void* const* d_in, const int* in_sizes, int n_in,
                              void* d_out, int out_size)
{
    (void)in_sizes; (void)n_in; (void)out_size;

    const float* X   = (const float*)d_in[0];
    const int*   pos = (const int*)d_in[2];
    const float* Wq  = (const float*)d_in[3];
    const float* Wk  = (const float*)d_in[4];
    const float* Wv  = (const float*)d_in[5];
    const float* Wo  = (const float*)d_in[6];
    float* out = (float*)d_out;

    float *Qd, *Kd, *Vd, *Ad;
    __nv_bfloat16 *A2d, *W2qd, *W2kd, *W2vd, *W2od, *Q2d, *K2d, *Vbd;
    cudaGetSymbolAddress((void**)&Qd, g_Q);
    cudaGetSymbolAddress((void**)&Kd, g_K);
    cudaGetSymbolAddress((void**)&Vd, g_V);
    cudaGetSymbolAddress((void**)&Ad, g_A);
    cudaGetSymbolAddress((void**)&A2d, g_A2);
    cudaGetSymbolAddress((void**)&W2qd, g_W2q);
    cudaGetSymbolAddress((void**)&W2kd, g_W2k);
    cudaGetSymbolAddress((void**)&W2vd, g_W2v);
    cudaGetSymbolAddress((void**)&W2od, g_W2o);
    cudaGetSymbolAddress((void**)&Q2d, g_Q2);
    cudaGetSymbolAddress((void**)&K2d, g_K2a);
    cudaGetSymbolAddress((void**)&Vbd, g_Vb);

    cudaFuncSetAttribute(gemm_mma, cudaFuncAttributeMaxDynamicSharedMemorySize,
                         GSMEM);
    cudaFuncSetAttribute(flash2, cudaFuncAttributeMaxDynamicSharedMemorySize,
                         FSMEM);

    // Splits
    split_bf16<<<(S_LEN * 1024) / 256, 256>>>(X, A2d, S_LEN * 1024);
    split_bf16_w<<<(HDIM * 1024) / 256, 256>>>(Wq, W2qd, HDIM * 1024);
    split_bf16_w<<<(HDIM * 1024) / 256, 256>>>(Wk, W2kd, HDIM * 1024);
    split_bf16_w<<<(HDIM * 1024) / 256, 256>>>(Wv, W2vd, HDIM * 1024);
    split_bf16_w<<<(HDIM * 1024) / 256, 256>>>(Wo, W2od, HDIM * 1024);

    dim3 ggrid(HDIM / BN, S_LEN / BM);

    gemm_mma<<<ggrid, 256, GSMEM>>>(A2d, W2qd, Qd);
    gemm_mma<<<ggrid, 256, GSMEM>>>(A2d, W2kd, Kd);
    gemm_mma<<<ggrid, 256, GSMEM>>>(A2d, W2vd, Vd);

    // RoPE + head-dim split (fused); V -> split bf16
    rope_split_qk<<<(S_LEN * NHEADS * 16) / 256, 256>>>(Qd, Kd, pos, Q2d, K2d);
    conv_v<<<(S_LEN * 1024) / 256, 256>>>(Vd, Vbd);

    // Tensor-core causal flash attention (fully split)
    flash2<<<dim3(NHEADS, S_LEN / 64), 256, FSMEM>>>(Q2d, K2d, Vbd, Ad);

    // O projection
    split_bf16<<<(S_LEN * 1024) / 256, 256>>>(Ad, A2d, S_LEN * 1024);
    gemm_mma<<<ggrid, 256, GSMEM>>>(A2d, W2od, out);
}

// round 8
// speedup vs baseline: 3.0360x; 1.0608x over previous
#include <cuda_runtime.h>
#include <cuda_bf16.h>
#include <math.h>
#include <stdint.h>

// Problem constants
#define S_LEN  2048
#define HDIM   4096     // hidden = NH*HD
#define NHEADS 32
#define HEADD  128
#define HD2    256      // head-dim split storage: [hi(128) | lo(128)]

#define KSEG   4096     // one split segment
#define KST2   8192     // storage row stride: [hi | lo]

// Scratch (device globals: allocation-free rule)
__device__ float g_Q[S_LEN * HDIM];
__device__ float g_K[S_LEN * HDIM];
__device__ float g_V[S_LEN * HDIM];
__device__ float g_A[S_LEN * HDIM];
__device__ __nv_bfloat16 g_A2[S_LEN * KST2];           // activations [hi|lo]
__device__ __nv_bfloat16 g_W2q[HDIM * KST2];           // weights [hi|lo]
__device__ __nv_bfloat16 g_W2k[HDIM * KST2];
__device__ __nv_bfloat16 g_W2v[HDIM * KST2];
__device__ __nv_bfloat16 g_W2o[HDIM * KST2];
__device__ __nv_bfloat16 g_Q2[NHEADS * S_LEN * HD2];   // [h][s][Qh|Ql]
__device__ __nv_bfloat16 g_K2a[NHEADS * S_LEN * HD2];  // [h][s][Kh|Kl]
__device__ __nv_bfloat16 g_Vb[NHEADS * S_LEN * HD2];   // [h][s][Vh|Vl]

// ===========================================================================
// PTX helpers (base PTX only)
// ===========================================================================
__device__ __forceinline__ uint32_t smem_u32(const void* p) {
    uint32_t a;
    asm("{ .reg .u64 t; cvta.to.shared.u64 t, %1; cvt.u32.u64 %0, t; }" : "=r"(a) : "l"(p));
    return a;
}
__device__ __forceinline__ void cp_async16(uint32_t dst, const void* src) {
    asm volatile("cp.async.cg.shared.global [%0], [%1], 16;" :: "r"(dst), "l"(src));
}
__device__ __forceinline__ void cp_commit() {
    asm volatile("cp.async.commit_group;" ::: "memory");
}
template <int N> __device__ __forceinline__ void cp_wait() {
    asm volatile("cp.async.wait_group %0;" :: "n"(N) : "memory");
}
__device__ __forceinline__ void ldsm_x4(uint32_t& r0, uint32_t& r1, uint32_t& r2,
                                        uint32_t& r3, uint32_t addr) {
    asm volatile("ldmatrix.sync.aligned.m8n8.x4.shared.b16 {%0,%1,%2,%3}, [%4];"
                 : "=r"(r0), "=r"(r1), "=r"(r2), "=r"(r3) : "r"(addr));
}
__device__ __forceinline__ void ldsm_x4t(uint32_t& r0, uint32_t& r1, uint32_t& r2,
                                         uint32_t& r3, uint32_t addr) {
    asm volatile("ldmatrix.sync.aligned.m8n8.x4.trans.shared.b16 {%0,%1,%2,%3}, [%4];"
                 : "=r"(r0), "=r"(r1), "=r"(r2), "=r"(r3) : "r"(addr));
}
__device__ __forceinline__ void mma16816(float* c, const uint32_t* a, const uint32_t* b) {
    asm volatile(
        "mma.sync.aligned.m16n8k16.row.col.f32.bf16.bf16.f32 "
        "{%0,%1,%2,%3}, {%4,%5,%6,%7}, {%8,%9}, {%0,%1,%2,%3};"
        : "+f"(c[0]), "+f"(c[1]), "+f"(c[2]), "+f"(c[3])
        : "r"(a[0]), "r"(a[1]), "r"(a[2]), "r"(a[3]), "r"(b[0]), "r"(b[1]));
}

__device__ __forceinline__ uint32_t pkb(__nv_bfloat16 a, __nv_bfloat16 b) {
    __nv_bfloat162 t = __halves2bfloat162(a, b);
    return *reinterpret_cast<uint32_t*>(&t);
}
__device__ __forceinline__ void split2(float x, __nv_bfloat16& h, __nv_bfloat16& l) {
    h = __float2bfloat16_rn(x);
    l = __float2bfloat16_rn(x - __bfloat162float(h));
}

// ===========================================================================
// fp32 [R,4096] -> bf16 [R, hi(4096)|lo(4096)]
// ===========================================================================
__global__ void __launch_bounds__(256) split_hilo(const float* __restrict__ src,
                                                  __nv_bfloat16* __restrict__ dst,
                                                  int total4)
{
    int i = blockIdx.x * 256 + threadIdx.x;
    if (i >= total4) return;
    int row = i >> 10;
    int c4  = (i & 1023) << 2;
    float4 v = ((const float4*)src)[i];
    float in[4] = {v.x, v.y, v.z, v.w};
    __nv_bfloat16 h[4], l[4];
#pragma unroll
    for (int j = 0; j < 4; ++j) split2(in[j], h[j], l[j]);
    size_t b = (size_t)row * KST2 + c4;
    *(uint2*)(dst + b)        = make_uint2(pkb(h[0], h[1]), pkb(h[2], h[3]));
    *(uint2*)(dst + b + KSEG) = make_uint2(pkb(l[0], l[1]), pkb(l[2], l[3]));
}

// ===========================================================================
// mma.sync bf16x3 GEMM: C = AhBh + AhBl + AlBh via 3 K-segments of 4096.
// CTA 128x128, BK=32, 256 threads (8 warps 2x4, warp tile 64x32).
// SMEM rows padded to 80B. 4-stage cp.async pipeline. 2 CTAs/SM.
// ===========================================================================
#define BM 128
#define BN 128
#define BK 32
#define NITER   384                // 3 segments x 128 iters
#define GSTAGES 4
#define ROWB    80
#define ASZ     (BM * ROWB)
#define STAGE   (2 * ASZ)
#define GSMEM   (GSTAGES * STAGE)  // 81920

// Segment select: iters 0-127 (Ah,Bh), 128-255 (Ah,Bl), 256-383 (Al,Bh)
__device__ __forceinline__ void g_load_stage(uint32_t sb,
                                             const __nv_bfloat16* __restrict__ A2,
                                             const __nv_bfloat16* __restrict__ B2,
                                             int m0, int n0, int j, int t)
{
    const int seg  = j >> 7;
    const int kloc = (j & 127) * BK;
    const int aoff = (seg == 2) ? KSEG : 0;
    const int boff = (seg == 1) ? KSEG : 0;
#pragma unroll
    for (int i = 0; i < 2; ++i) {
        int c   = t + (i << 8);
        int row = c >> 2;
        int kc  = c & 3;
        cp_async16(sb + row * ROWB + kc * 16,
                   A2 + (size_t)(m0 + row) * KST2 + aoff + kloc + kc * 8);
    }
#pragma unroll
    for (int i = 0; i < 2; ++i) {
        int c   = t + (i << 8);
        int row = c >> 2;
        int kc  = c & 3;
        cp_async16(sb + ASZ + row * ROWB + kc * 16,
                   B2 + (size_t)(n0 + row) * KST2 + boff + kloc + kc * 8);
    }
    cp_commit();
}

__global__ void __launch_bounds__(256, 2)
gemm_mma(const __nv_bfloat16* __restrict__ A2,
         const __nv_bfloat16* __restrict__ B2,
         float* __restrict__ C)
{
    extern __shared__ char smraw[];
    const uint32_t base = smem_u32(smraw);
    const int t    = threadIdx.x;
    const int wid  = t >> 5;
    const int lane = t & 31;
    const int m0   = blockIdx.y * BM;
    const int n0   = blockIdx.x * BN;
    const int wm   = (wid >> 2) * 64;
    const int wn   = (wid & 3) * 32;

    const int rA   = lane & 15;
    const int selA = lane >> 4;
    const int rB   = ((lane >> 4) << 3) | (lane & 7);
    const int selB = (lane >> 3) & 1;

    float acc[4][4][4];
#pragma unroll
    for (int mi = 0; mi < 4; ++mi)
#pragma unroll
        for (int nj = 0; nj < 4; ++nj)
#pragma unroll
            for (int q = 0; q < 4; ++q) acc[mi][nj][q] = 0.0f;

#pragma unroll
    for (int it = 0; it < GSTAGES - 1; ++it)
        g_load_stage(base + it * STAGE, A2, B2, m0, n0, it, t);

    for (int it = 0; it < NITER; ++it) {
        const int st = it & (GSTAGES - 1);
        cp_wait<GSTAGES - 2>();
        __syncthreads();

        const uint32_t stA = base + st * STAGE;
        const uint32_t stB = stA + ASZ;

#pragma unroll
        for (int kh = 0; kh < 2; ++kh) {
            uint32_t a[4][4];
#pragma unroll
            for (int mi = 0; mi < 4; ++mi)
                ldsm_x4(a[mi][0], a[mi][1], a[mi][2], a[mi][3],
                        stA + (uint32_t)((wm + mi * 16 + rA) * ROWB
                                         + (kh * 2 + selA) * 16));
            uint32_t b[2][4];
#pragma unroll
            for (int p = 0; p < 2; ++p)
                ldsm_x4(b[p][0], b[p][1], b[p][2], b[p][3],
                        stB + (uint32_t)((wn + p * 16 + rB) * ROWB
                                         + (kh * 2 + selB) * 16));
#pragma unroll
            for (int mi = 0; mi < 4; ++mi) {
#pragma unroll
                for (int nj = 0; nj < 4; ++nj) {
                    const uint32_t* bf = &b[nj >> 1][(nj & 1) << 1];
                    mma16816(acc[mi][nj], a[mi], bf);
                }
            }
        }

        const int j = it + GSTAGES - 1;
        if (j < NITER)
            g_load_stage(base + (j & (GSTAGES - 1)) * STAGE, A2, B2, m0, n0, j, t);
    }

    const int er = lane >> 2;
    const int ec = (lane & 3) << 1;
#pragma unroll
    for (int mi = 0; mi < 4; ++mi) {
#pragma unroll
        for (int nj = 0; nj < 4; ++nj) {
            size_t r0 = (size_t)(m0 + wm + mi * 16 + er) * HDIM
                        + (n0 + wn + nj * 8 + ec);
            *(float2*)&C[r0]            = make_float2(acc[mi][nj][0], acc[mi][nj][1]);
            *(float2*)&C[r0 + 8 * HDIM] = make_float2(acc[mi][nj][2], acc[mi][nj][3]);
        }
    }
}

// ===========================================================================
// Fused RoPE + head-dim split: Q2[h][s][256]=[Qh|Ql]*scale, K2=[Kh|Kl]
// ===========================================================================
#define ATT_SCALE 0.08838834764831843f   // 1/sqrt(128)

__global__ void __launch_bounds__(256) rope_split_qk(
    const float* __restrict__ Q, const float* __restrict__ K,
    const int* __restrict__ pos,
    __nv_bfloat16* __restrict__ Q2, __nv_bfloat16* __restrict__ K2o)
{
    int idx = blockIdx.x * 256 + threadIdx.x;        // S*NH*16
    if (idx >= S_LEN * NHEADS * 16) return;
    int j4 = (idx & 15) << 2;                         // 0..60
    int h  = (idx >> 4) & (NHEADS - 1);
    int s  = idx >> 9;
    int p  = pos[s];

    float sn[4], cs[4];
#pragma unroll
    for (int i = 0; i < 4; ++i) {
        float inv = 1.0f / powf(10000.0f, (float)(j4 + i) * (1.0f / 64.0f));
        sincosf((float)p * inv, &sn[i], &cs[i]);
    }

    size_t gb = (size_t)s * HDIM + (size_t)h * HEADD + j4;
    float4 qa4 = *(const float4*)&Q[gb];
    float4 qb4 = *(const float4*)&Q[gb + 64];
    float4 ka4 = *(const float4*)&K[gb];
    float4 kb4 = *(const float4*)&K[gb + 64];
    float qa[4] = {qa4.x, qa4.y, qa4.z, qa4.w};
    float qb[4] = {qb4.x, qb4.y, qb4.z, qb4.w};
    float ka[4] = {ka4.x, ka4.y, ka4.z, ka4.w};
    float kb[4] = {kb4.x, kb4.y, kb4.z, kb4.w};

    __nv_bfloat16 qah[4], qal[4], qbh[4], qbl[4];
    __nv_bfloat16 kah[4], kal[4], kbh[4], kbl[4];
#pragma unroll
    for (int i = 0; i < 4; ++i) {
        float r1 = (qa[i] * cs[i] - qb[i] * sn[i]) * ATT_SCALE;
        float r2 = (qb[i] * cs[i] + qa[i] * sn[i]) * ATT_SCALE;
        split2(r1, qah[i], qal[i]);
        split2(r2, qbh[i], qbl[i]);
        float t1 = ka[i] * cs[i] - kb[i] * sn[i];
        float t2 = kb[i] * cs[i] + ka[i] * sn[i];
        split2(t1, kah[i], kal[i]);
        split2(t2, kbh[i], kbl[i]);
    }

    size_t ob = ((size_t)h * S_LEN + s) * HD2 + j4;
    // [hi(0..127) | lo(128..255)]
    *(uint2*)(Q2 + ob)       = make_uint2(pkb(qah[0], qah[1]), pkb(qah[2], qah[3]));
    *(uint2*)(Q2 + ob + 64)  = make_uint2(pkb(qbh[0], qbh[1]), pkb(qbh[2], qbh[3]));
    *(uint2*)(Q2 + ob + 128) = make_uint2(pkb(qal[0], qal[1]), pkb(qal[2], qal[3]));
    *(uint2*)(Q2 + ob + 192) = make_uint2(pkb(qbl[0], qbl[1]), pkb(qbl[2], qbl[3]));

    *(uint2*)(K2o + ob)       = make_uint2(pkb(kah[0], kah[1]), pkb(kah[2], kah[3]));
    *(uint2*)(K2o + ob + 64)  = make_uint2(pkb(kbh[0], kbh[1]), pkb(kbh[2], kbh[3]));
    *(uint2*)(K2o + ob + 128) = make_uint2(pkb(kal[0], kal[1]), pkb(kal[2], kal[3]));
    *(uint2*)(K2o + ob + 192) = make_uint2(pkb(kbl[0], kbl[1]), pkb(kbl[2], kbl[3]));
}

// V fp32 [s][4096] -> split bf16 [h][s][Vh(128)|Vl(128)]
__global__ void __launch_bounds__(256) conv_v(const float* __restrict__ V,
                                              __nv_bfloat16* __restrict__ Vb)
{
    int i = blockIdx.x * 256 + threadIdx.x;   // S*1024
    if (i >= S_LEN * 1024) return;
    int s  = i >> 10;
    int hc = i & 1023;
    int h  = hc >> 5;
    int c4 = (hc & 31) << 2;
    float4 v = ((const float4*)V)[i];
    float in[4] = {v.x, v.y, v.z, v.w};
    __nv_bfloat16 hh[4], ll[4];
#pragma unroll
    for (int j = 0; j < 4; ++j) split2(in[j], hh[j], ll[j]);
    size_t ob = ((size_t)h * S_LEN + s) * HD2 + c4;
    *(uint2*)(Vb + ob)       = make_uint2(pkb(hh[0], hh[1]), pkb(hh[2], hh[3]));
    *(uint2*)(Vb + ob + 128) = make_uint2(pkb(ll[0], ll[1]), pkb(ll[2], ll[3]));
}

// ===========================================================================
// Flash attention v3 (tensor cores, fully split) — validated R7.
// ===========================================================================
#define NEG_BIG (-3.0e38f)
#define FROW2  528
#define FROWP  272
#define OFF_K2S  (64 * FROW2)
#define OFF_VS   (OFF_K2S + 2 * 64 * FROW2)
#define OFF_SS   (OFF_VS + 2 * 64 * FROW2)
#define OFF_PS   (OFF_SS + 64 * 68 * 4)
#define OFF_RW   (OFF_PS + 64 * FROWP)
#define FSMEM    (OFF_RW + 3 * 64 * 4)

__device__ __forceinline__ void f_load_kv(uint32_t sb, int buf,
                                          const __nv_bfloat16* __restrict__ K2g,
                                          const __nv_bfloat16* __restrict__ Vg,
                                          int t)
{
    uint32_t kb = sb + OFF_K2S + buf * (64 * FROW2);
    for (int c = t; c < 64 * 32; c += 256) {
        int r = c >> 5, ch = c & 31;
        cp_async16(kb + r * FROW2 + ch * 16,
                   (const char*)K2g + (size_t)r * (HD2 * 2) + ch * 16);
    }
    uint32_t vb = sb + OFF_VS + buf * (64 * FROW2);
    for (int c = t; c < 64 * 32; c += 256) {
        int r = c >> 5, ch = c & 31;
        cp_async16(vb + r * FROW2 + ch * 16,
                   (const char*)Vg + (size_t)r * (HD2 * 2) + ch * 16);
    }
    cp_commit();
}

__global__ void __launch_bounds__(256) flash2(
    const __nv_bfloat16* __restrict__ Q2,
    const __nv_bfloat16* __restrict__ K2g,
    const __nv_bfloat16* __restrict__ Vb,
    float* __restrict__ O)
{
    extern __shared__ char smraw[];
    const uint32_t sb = smem_u32(smraw);
    float* Ss  = (float*)(smraw + OFF_SS);
    __nv_bfloat16* Ps = (__nv_bfloat16*)(smraw + OFF_PS);
    float* mrow = (float*)(smraw + OFF_RW);
    float* lrow = mrow + 64;
    float* srow = lrow + 64;

    const int h  = blockIdx.x;
    const int qb = (gridDim.y - 1) - blockIdx.y;   // heavy blocks first
    const int q0 = qb * 64;
    const int t = threadIdx.x, wid = t >> 5, lane = t & 31;
    const int wm = (wid >> 2) * 32;
    const int wn = (wid & 3) * 16;
    const int wnv = (wid & 3) * 32;
    const int rA = lane & 15, selA = lane >> 4;
    const int rB = ((lane >> 4) << 3) | (lane & 7), selB = (lane >> 3) & 1;
    const int er = lane >> 2, ec = (lane & 3) << 1;

    const __nv_bfloat16* Qg = Q2 + ((size_t)h * S_LEN + q0) * HD2;
    for (int c = t; c < 64 * 32; c += 256) {
        int r = c >> 5, ch = c & 31;
        cp_async16(sb + r * FROW2 + ch * 16,
                   (const char*)Qg + (size_t)r * (HD2 * 2) + ch * 16);
    }
    cp_commit();
    if (t < 64) { mrow[t] = NEG_BIG; lrow[t] = 0.0f; }

    f_load_kv(sb, 0, K2g + ((size_t)h * S_LEN) * HD2,
              Vb + ((size_t)h * S_LEN) * HD2, t);

    float oacc[2][4][4];
#pragma unroll
    for (int mi = 0; mi < 2; ++mi)
#pragma unroll
        for (int nj = 0; nj < 4; ++nj)
#pragma unroll
            for (int q = 0; q < 4; ++q) oacc[mi][nj][q] = 0.0f;

    for (int kb = 0; kb <= qb; ++kb) {
        const int buf = kb & 1;
        cp_wait<0>();
        __syncthreads();

        if (kb + 1 <= qb)
            f_load_kv(sb, buf ^ 1,
                      K2g + ((size_t)h * S_LEN + (kb + 1) * 64) * HD2,
                      Vb + ((size_t)h * S_LEN + (kb + 1) * 64) * HD2, t);

        const uint32_t kbase = sb + OFF_K2S + buf * (64 * FROW2);
        const uint32_t vbase = sb + OFF_VS + buf * (64 * FROW2);

        float sacc[2][2][4];
#pragma unroll
        for (int mi = 0; mi < 2; ++mi)
#pragma unroll
            for (int nj = 0; nj < 2; ++nj)
#pragma unroll
                for (int q = 0; q < 4; ++q) sacc[mi][nj][q] = 0.0f;

        const uint32_t sAoff[3] = {0u, 0u, 256u};
        const uint32_t sBoff[3] = {0u, 256u, 0u};
#pragma unroll
        for (int ps = 0; ps < 3; ++ps) {
#pragma unroll
            for (int k16 = 0; k16 < 8; ++k16) {
                uint32_t a[2][4], b[4];
#pragma unroll
                for (int mi = 0; mi < 2; ++mi)
                    ldsm_x4(a[mi][0], a[mi][1], a[mi][2], a[mi][3],
                            sb + (uint32_t)((wm + mi * 16 + rA) * FROW2)
                               + sAoff[ps] + k16 * 32 + selA * 16);
                ldsm_x4(b[0], b[1], b[2], b[3],
                        kbase + (uint32_t)((wn + rB) * FROW2)
                              + sBoff[ps] + k16 * 32 + selB * 16);
#pragma unroll
                for (int mi = 0; mi < 2; ++mi)
#pragma unroll
                    for (int nj = 0; nj < 2; ++nj)
                        mma16816(sacc[mi][nj], a[mi], &b[nj << 1]);
            }
        }

        const bool diag = (kb == qb);
#pragma unroll
        for (int mi = 0; mi < 2; ++mi) {
#pragma unroll
            for (int nj = 0; nj < 2; ++nj) {
                int row = wm + mi * 16 + er;
                int col = wn + nj * 8 + ec;
                float v0 = sacc[mi][nj][0], v1 = sacc[mi][nj][1];
                float v2 = sacc[mi][nj][2], v3 = sacc[mi][nj][3];
                if (diag) {
                    if (col > row)     v0 = NEG_BIG;
                    if (col + 1 > row) v1 = NEG_BIG;
                    if (col > row + 8)     v2 = NEG_BIG;
                    if (col + 1 > row + 8) v3 = NEG_BIG;
                }
                Ss[row * 68 + col]       = v0;
                Ss[row * 68 + col + 1]   = v1;
                Ss[(row + 8) * 68 + col]     = v2;
                Ss[(row + 8) * 68 + col + 1] = v3;
            }
        }
        __syncthreads();

        {
            int r  = t >> 2;
            int qd = t & 3;
            float* srw = &Ss[r * 68 + qd * 16];
            __nv_bfloat16* prw = &Ps[r * 136 + qd * 16];
            float vals[16];
            float mx = NEG_BIG;
#pragma unroll
            for (int i = 0; i < 16; ++i) { vals[i] = srw[i]; mx = fmaxf(mx, vals[i]); }
            mx = fmaxf(mx, __shfl_xor_sync(0xffffffffu, mx, 1));
            mx = fmaxf(mx, __shfl_xor_sync(0xffffffffu, mx, 2));
            float mold = mrow[r];
            float mnew = fmaxf(mold, mx);
            float sum = 0.0f;
#pragma unroll
            for (int i = 0; i < 16; ++i) {
                float p = __expf(vals[i] - mnew);
                __nv_bfloat16 ph, pl;
                split2(p, ph, pl);
                prw[i]      = ph;
                prw[i + 64] = pl;
                sum += p;
            }
            sum += __shfl_xor_sync(0xffffffffu, sum, 1);
            sum += __shfl_xor_sync(0xffffffffu, sum, 2);
            float corr = __expf(mold - mnew);
            if (qd == 0) {
                mrow[r] = mnew;
                lrow[r] = lrow[r] * corr + sum;
                srow[r] = corr;
            }
        }
        __syncthreads();

#pragma unroll
        for (int mi = 0; mi < 2; ++mi) {
            float c0 = srow[wm + mi * 16 + er];
            float c1 = srow[wm + mi * 16 + er + 8];
#pragma unroll
            for (int nj = 0; nj < 4; ++nj) {
                oacc[mi][nj][0] *= c0; oacc[mi][nj][1] *= c0;
                oacc[mi][nj][2] *= c1; oacc[mi][nj][3] *= c1;
            }
        }

        const int vkr = ((lane >> 3) & 1) * 8 + (lane & 7);
        const int vnc = (lane >> 4) * 8;
        const uint32_t pAoff[3] = {0u, 0u, 128u};
        const uint32_t pVoff[3] = {0u, 256u, 0u};
#pragma unroll
        for (int ps = 0; ps < 3; ++ps) {
#pragma unroll
            for (int kk = 0; kk < 4; ++kk) {
                uint32_t a[2][4], b0[4], b1[4];
#pragma unroll
                for (int mi = 0; mi < 2; ++mi)
                    ldsm_x4(a[mi][0], a[mi][1], a[mi][2], a[mi][3],
                            sb + OFF_PS + (uint32_t)((wm + mi * 16 + rA) * FROWP)
                               + pAoff[ps] + kk * 32 + selA * 16);
                uint32_t vaddr = vbase + (uint32_t)((kk * 16 + vkr) * FROW2)
                               + pVoff[ps];
                ldsm_x4t(b0[0], b0[1], b0[2], b0[3], vaddr + (wnv + vnc) * 2);
                ldsm_x4t(b1[0], b1[1], b1[2], b1[3], vaddr + (wnv + 16 + vnc) * 2);
#pragma unroll
                for (int mi = 0; mi < 2; ++mi) {
                    mma16816(oacc[mi][0], a[mi], &b0[0]);
                    mma16816(oacc[mi][1], a[mi], &b0[2]);
                    mma16816(oacc[mi][2], a[mi], &b1[0]);
                    mma16816(oacc[mi][3], a[mi], &b1[2]);
                }
            }
        }
    }

#pragma unroll
    for (int mi = 0; mi < 2; ++mi) {
        float l0 = 1.0f / lrow[wm + mi * 16 + er];
        float l1 = 1.0f / lrow[wm + mi * 16 + er + 8];
#pragma unroll
        for (int nj = 0; nj < 4; ++nj) {
            size_t r0 = (size_t)(q0 + wm + mi * 16 + er) * HDIM
                        + (size_t)h * HEADD + wnv + nj * 8 + ec;
            *(float2*)&O[r0]            = make_float2(oacc[mi][nj][0] * l0,
                                                      oacc[mi][nj][1] * l0);
            *(float2*)&O[r0 + 8 * HDIM] = make_float2(oacc[mi][nj][2] * l1,
                                                      oacc[mi][nj][3] * l1);
        }
    }
}

// ===========================================================================
// Launch
// ===========================================================================
extern "C" void kernel_launch(void* const* d_in, const int* in_sizes, int n_in,
                              void* d_out, int out_size)
{
    (void)in_sizes; (void)n_in; (void)out_size;

    const float* X   = (const float*)d_in[0];
    const int*   pos = (const int*)d_in[2];
    const float* Wq  = (const float*)d_in[3];
    const float* Wk  = (const float*)d_in[4];
    const float* Wv  = (const float*)d_in[5];
    const float* Wo  = (const float*)d_in[6];
    float* out = (float*)d_out;

    float *Qd, *Kd, *Vd, *Ad;
    __nv_bfloat16 *A2d, *W2qd, *W2kd, *W2vd, *W2od, *Q2d, *K2d, *Vbd;
    cudaGetSymbolAddress((void**)&Qd, g_Q);
    cudaGetSymbolAddress((void**)&Kd, g_K);
    cudaGetSymbolAddress((void**)&Vd, g_V);
    cudaGetSymbolAddress((void**)&Ad, g_A);
    cudaGetSymbolAddress((void**)&A2d, g_A2);
    cudaGetSymbolAddress((void**)&W2qd, g_W2q);
    cudaGetSymbolAddress((void**)&W2kd, g_W2k);
    cudaGetSymbolAddress((void**)&W2vd, g_W2v);
    cudaGetSymbolAddress((void**)&W2od, g_W2o);
    cudaGetSymbolAddress((void**)&Q2d, g_Q2);
    cudaGetSymbolAddress((void**)&K2d, g_K2a);
    cudaGetSymbolAddress((void**)&Vbd, g_Vb);

    cudaFuncSetAttribute(gemm_mma, cudaFuncAttributeMaxDynamicSharedMemorySize,
                         GSMEM);
    cudaFuncSetAttribute(flash2, cudaFuncAttributeMaxDynamicSharedMemorySize,
                         FSMEM);

    // Splits (all [hi|lo] now)
    split_hilo<<<(S_LEN * 1024) / 256, 256>>>(X, A2d, S_LEN * 1024);
    split_hilo<<<(HDIM * 1024) / 256, 256>>>(Wq, W2qd, HDIM * 1024);
    split_hilo<<<(HDIM * 1024) / 256, 256>>>(Wk, W2kd, HDIM * 1024);
    split_hilo<<<(HDIM * 1024) / 256, 256>>>(Wv, W2vd, HDIM * 1024);
    split_hilo<<<(HDIM * 1024) / 256, 256>>>(Wo, W2od, HDIM * 1024);

    dim3 ggrid(HDIM / BN, S_LEN / BM);

    gemm_mma<<<ggrid, 256, GSMEM>>>(A2d, W2qd, Qd);
    gemm_mma<<<ggrid, 256, GSMEM>>>(A2d, W2kd, Kd);
    gemm_mma<<<ggrid, 256, GSMEM>>>(A2d, W2vd, Vd);

    // RoPE + head-dim split (fused); V -> split bf16
    rope_split_qk<<<(S_LEN * NHEADS * 16) / 256, 256>>>(Qd, Kd, pos, Q2d, K2d);
    conv_v<<<(S_LEN * 1024) / 256, 256>>>(Vd, Vbd);

    // Tensor-core causal flash attention (fully split)
    flash2<<<dim3(NHEADS, S_LEN / 64), 256, FSMEM>>>(Q2d, K2d, Vbd, Ad);

    // O projection
    split_hilo<<<(S_LEN * 1024) / 256, 256>>>(Ad, A2d, S_LEN * 1024);
    gemm_mma<<<ggrid, 256, GSMEM>>>(A2d, W2od, out);
}

// round 9
// speedup vs baseline: 3.7239x; 1.2266x over previous
#include <cuda_runtime.h>
#include <cuda_bf16.h>
#include <math.h>
#include <stdint.h>

// Problem constants
#define S_LEN  2048
#define HDIM   4096     // hidden = NH*HD
#define NHEADS 32
#define HEADD  128
#define HD2    256      // head-dim split storage: [hi(128) | lo(128)]

#define KSEG   4096     // one split segment
#define KST2   8192     // storage row stride: [hi | lo]

// Scratch (device globals: allocation-free rule)
__device__ float g_Q[S_LEN * HDIM];
__device__ float g_K[S_LEN * HDIM];
__device__ float g_V[S_LEN * HDIM];
__device__ __nv_bfloat16 g_A2[S_LEN * KST2];           // activations [hi|lo]
__device__ __nv_bfloat16 g_W2q[HDIM * KST2];           // weights [hi|lo]
__device__ __nv_bfloat16 g_W2k[HDIM * KST2];
__device__ __nv_bfloat16 g_W2v[HDIM * KST2];
__device__ __nv_bfloat16 g_W2o[HDIM * KST2];
__device__ __nv_bfloat16 g_Q2[NHEADS * S_LEN * HD2];   // [h][s][Qh|Ql]
__device__ __nv_bfloat16 g_K2a[NHEADS * S_LEN * HD2];  // [h][s][Kh|Kl]
__device__ __nv_bfloat16 g_Vb[NHEADS * S_LEN * HD2];   // [h][s][Vh|Vl]

// ===========================================================================
// PTX helpers (base PTX only)
// ===========================================================================
__device__ __forceinline__ uint32_t smem_u32(const void* p) {
    uint32_t a;
    asm("{ .reg .u64 t; cvta.to.shared.u64 t, %1; cvt.u32.u64 %0, t; }" : "=r"(a) : "l"(p));
    return a;
}
__device__ __forceinline__ void cp_async16(uint32_t dst, const void* src) {
    asm volatile("cp.async.cg.shared.global [%0], [%1], 16;" :: "r"(dst), "l"(src));
}
__device__ __forceinline__ void cp_commit() {
    asm volatile("cp.async.commit_group;" ::: "memory");
}
template <int N> __device__ __forceinline__ void cp_wait() {
    asm volatile("cp.async.wait_group %0;" :: "n"(N) : "memory");
}
__device__ __forceinline__ void ldsm_x4(uint32_t& r0, uint32_t& r1, uint32_t& r2,
                                        uint32_t& r3, uint32_t addr) {
    asm volatile("ldmatrix.sync.aligned.m8n8.x4.shared.b16 {%0,%1,%2,%3}, [%4];"
                 : "=r"(r0), "=r"(r1), "=r"(r2), "=r"(r3) : "r"(addr));
}
__device__ __forceinline__ void ldsm_x4t(uint32_t& r0, uint32_t& r1, uint32_t& r2,
                                         uint32_t& r3, uint32_t addr) {
    asm volatile("ldmatrix.sync.aligned.m8n8.x4.trans.shared.b16 {%0,%1,%2,%3}, [%4];"
                 : "=r"(r0), "=r"(r1), "=r"(r2), "=r"(r3) : "r"(addr));
}
__device__ __forceinline__ void mma16816(float* c, const uint32_t* a, const uint32_t* b) {
    asm volatile(
        "mma.sync.aligned.m16n8k16.row.col.f32.bf16.bf16.f32 "
        "{%0,%1,%2,%3}, {%4,%5,%6,%7}, {%8,%9}, {%0,%1,%2,%3};"
        : "+f"(c[0]), "+f"(c[1]), "+f"(c[2]), "+f"(c[3])
        : "r"(a[0]), "r"(a[1]), "r"(a[2]), "r"(a[3]), "r"(b[0]), "r"(b[1]));
}

__device__ __forceinline__ uint32_t pkb(__nv_bfloat16 a, __nv_bfloat16 b) {
    __nv_bfloat162 t = __halves2bfloat162(a, b);
    return *reinterpret_cast<uint32_t*>(&t);
}
__device__ __forceinline__ void split2(float x, __nv_bfloat16& h, __nv_bfloat16& l) {
    h = __float2bfloat16_rn(x);
    l = __float2bfloat16_rn(x - __bfloat162float(h));
}

// ===========================================================================
// fp32 [R,4096] -> bf16 [R, hi(4096)|lo(4096)]
// ===========================================================================
__global__ void __launch_bounds__(256) split_hilo(const float* __restrict__ src,
                                                  __nv_bfloat16* __restrict__ dst,
                                                  int total4)
{
    int i = blockIdx.x * 256 + threadIdx.x;
    if (i >= total4) return;
    int row = i >> 10;
    int c4  = (i & 1023) << 2;
    float4 v = ((const float4*)src)[i];
    float in[4] = {v.x, v.y, v.z, v.w};
    __nv_bfloat16 h[4], l[4];
#pragma unroll
    for (int j = 0; j < 4; ++j) split2(in[j], h[j], l[j]);
    size_t b = (size_t)row * KST2 + c4;
    *(uint2*)(dst + b)        = make_uint2(pkb(h[0], h[1]), pkb(h[2], h[3]));
    *(uint2*)(dst + b + KSEG) = make_uint2(pkb(l[0], l[1]), pkb(l[2], l[3]));
}

// ===========================================================================
// mma.sync bf16x3 GEMM v2: C = AhBh + AhBl + AlBh via 3 K-segments of 4096.
// CTA 128x128, BK=32, 128 threads (4 warps 2x2, warp tile 64x64).
// Crossbar/iter: 32KB ldsm + 16KB STS (~384cyc) < HMMA 512cyc -> tensor-bound.
// 4-stage cp.async pipeline, 2 CTAs/SM (reg budget 256 at 128thr).
// ===========================================================================
#define BM 128
#define BN 128
#define BK 32
#define NITER   384                // 3 segments x 128 iters
#define GSTAGES 4
#define ROWB    80
#define ASZ     (BM * ROWB)
#define STAGE   (2 * ASZ)
#define GSMEM   (GSTAGES * STAGE)  // 81920

// Segment select: iters 0-127 (Ah,Bh), 128-255 (Ah,Bl), 256-383 (Al,Bh)
__device__ __forceinline__ void g_load_stage(uint32_t sb,
                                             const __nv_bfloat16* __restrict__ A2,
                                             const __nv_bfloat16* __restrict__ B2,
                                             int m0, int n0, int j, int t)
{
    const int seg  = j >> 7;
    const int kloc = (j & 127) * BK;
    const int aoff = (seg == 2) ? KSEG : 0;
    const int boff = (seg == 1) ? KSEG : 0;
#pragma unroll
    for (int i = 0; i < 4; ++i) {                // A: 128 rows x 64B = 512 x 16B
        int c   = t + (i << 7);
        int row = c >> 2;
        int kc  = c & 3;
        cp_async16(sb + row * ROWB + kc * 16,
                   A2 + (size_t)(m0 + row) * KST2 + aoff + kloc + kc * 8);
    }
#pragma unroll
    for (int i = 0; i < 4; ++i) {                // B: 128 rows x 64B
        int c   = t + (i << 7);
        int row = c >> 2;
        int kc  = c & 3;
        cp_async16(sb + ASZ + row * ROWB + kc * 16,
                   B2 + (size_t)(n0 + row) * KST2 + boff + kloc + kc * 8);
    }
    cp_commit();
}

__global__ void __launch_bounds__(128, 2)
gemm_mma(const __nv_bfloat16* __restrict__ A2,
         const __nv_bfloat16* __restrict__ B2,
         float* __restrict__ C)
{
    extern __shared__ char smraw[];
    const uint32_t base = smem_u32(smraw);
    const int t    = threadIdx.x;
    const int wid  = t >> 5;
    const int lane = t & 31;
    const int m0   = blockIdx.y * BM;
    const int n0   = blockIdx.x * BN;
    const int wm   = (wid >> 1) * 64;    // 2x2 warp grid, 64x64 per warp
    const int wn   = (wid & 1) * 64;

    const int rA   = lane & 15;
    const int selA = lane >> 4;
    const int rB   = ((lane >> 4) << 3) | (lane & 7);
    const int selB = (lane >> 3) & 1;

    float acc[4][8][4];
#pragma unroll
    for (int mi = 0; mi < 4; ++mi)
#pragma unroll
        for (int nj = 0; nj < 8; ++nj)
#pragma unroll
            for (int q = 0; q < 4; ++q) acc[mi][nj][q] = 0.0f;

#pragma unroll
    for (int it = 0; it < GSTAGES - 1; ++it)
        g_load_stage(base + it * STAGE, A2, B2, m0, n0, it, t);

    for (int it = 0; it < NITER; ++it) {
        const int st = it & (GSTAGES - 1);
        cp_wait<GSTAGES - 2>();
        __syncthreads();

        const uint32_t stA = base + st * STAGE;
        const uint32_t stB = stA + ASZ;

#pragma unroll
        for (int kh = 0; kh < 2; ++kh) {
            uint32_t a[4][4];
#pragma unroll
            for (int mi = 0; mi < 4; ++mi)
                ldsm_x4(a[mi][0], a[mi][1], a[mi][2], a[mi][3],
                        stA + (uint32_t)((wm + mi * 16 + rA) * ROWB
                                         + (kh * 2 + selA) * 16));
            uint32_t b[4][4];
#pragma unroll
            for (int p = 0; p < 4; ++p)
                ldsm_x4(b[p][0], b[p][1], b[p][2], b[p][3],
                        stB + (uint32_t)((wn + p * 16 + rB) * ROWB
                                         + (kh * 2 + selB) * 16));
#pragma unroll
            for (int mi = 0; mi < 4; ++mi) {
#pragma unroll
                for (int p = 0; p < 4; ++p) {
                    mma16816(acc[mi][2 * p],     a[mi], &b[p][0]);
                    mma16816(acc[mi][2 * p + 1], a[mi], &b[p][2]);
                }
            }
        }

        const int j = it + GSTAGES - 1;
        if (j < NITER)
            g_load_stage(base + (j & (GSTAGES - 1)) * STAGE, A2, B2, m0, n0, j, t);
    }

    const int er = lane >> 2;
    const int ec = (lane & 3) << 1;
#pragma unroll
    for (int mi = 0; mi < 4; ++mi) {
#pragma unroll
        for (int nj = 0; nj < 8; ++nj) {
            size_t r0 = (size_t)(m0 + wm + mi * 16 + er) * HDIM
                        + (n0 + wn + nj * 8 + ec);
            *(float2*)&C[r0]            = make_float2(acc[mi][nj][0], acc[mi][nj][1]);
            *(float2*)&C[r0 + 8 * HDIM] = make_float2(acc[mi][nj][2], acc[mi][nj][3]);
        }
    }
}

// ===========================================================================
// Fused RoPE + head-dim split: Q2[h][s][256]=[Qh|Ql]*scale, K2=[Kh|Kl]
// ===========================================================================
#define ATT_SCALE 0.08838834764831843f   // 1/sqrt(128)

__global__ void __launch_bounds__(256) rope_split_qk(
    const float* __restrict__ Q, const float* __restrict__ K,
    const int* __restrict__ pos,
    __nv_bfloat16* __restrict__ Q2, __nv_bfloat16* __restrict__ K2o)
{
    int idx = blockIdx.x * 256 + threadIdx.x;        // S*NH*16
    if (idx >= S_LEN * NHEADS * 16) return;
    int j4 = (idx & 15) << 2;                         // 0..60
    int h  = (idx >> 4) & (NHEADS - 1);
    int s  = idx >> 9;
    int p  = pos[s];

    float sn[4], cs[4];
#pragma unroll
    for (int i = 0; i < 4; ++i) {
        float inv = 1.0f / powf(10000.0f, (float)(j4 + i) * (1.0f / 64.0f));
        sincosf((float)p * inv, &sn[i], &cs[i]);
    }

    size_t gb = (size_t)s * HDIM + (size_t)h * HEADD + j4;
    float4 qa4 = *(const float4*)&Q[gb];
    float4 qb4 = *(const float4*)&Q[gb + 64];
    float4 ka4 = *(const float4*)&K[gb];
    float4 kb4 = *(const float4*)&K[gb + 64];
    float qa[4] = {qa4.x, qa4.y, qa4.z, qa4.w};
    float qb[4] = {qb4.x, qb4.y, qb4.z, qb4.w};
    float ka[4] = {ka4.x, ka4.y, ka4.z, ka4.w};
    float kb[4] = {kb4.x, kb4.y, kb4.z, kb4.w};

    __nv_bfloat16 qah[4], qal[4], qbh[4], qbl[4];
    __nv_bfloat16 kah[4], kal[4], kbh[4], kbl[4];
#pragma unroll
    for (int i = 0; i < 4; ++i) {
        float r1 = (qa[i] * cs[i] - qb[i] * sn[i]) * ATT_SCALE;
        float r2 = (qb[i] * cs[i] + qa[i] * sn[i]) * ATT_SCALE;
        split2(r1, qah[i], qal[i]);
        split2(r2, qbh[i], qbl[i]);
        float t1 = ka[i] * cs[i] - kb[i] * sn[i];
        float t2 = kb[i] * cs[i] + ka[i] * sn[i];
        split2(t1, kah[i], kal[i]);
        split2(t2, kbh[i], kbl[i]);
    }

    size_t ob = ((size_t)h * S_LEN + s) * HD2 + j4;
    *(uint2*)(Q2 + ob)       = make_uint2(pkb(qah[0], qah[1]), pkb(qah[2], qah[3]));
    *(uint2*)(Q2 + ob + 64)  = make_uint2(pkb(qbh[0], qbh[1]), pkb(qbh[2], qbh[3]));
    *(uint2*)(Q2 + ob + 128) = make_uint2(pkb(qal[0], qal[1]), pkb(qal[2], qal[3]));
    *(uint2*)(Q2 + ob + 192) = make_uint2(pkb(qbl[0], qbl[1]), pkb(qbl[2], qbl[3]));

    *(uint2*)(K2o + ob)       = make_uint2(pkb(kah[0], kah[1]), pkb(kah[2], kah[3]));
    *(uint2*)(K2o + ob + 64)  = make_uint2(pkb(kbh[0], kbh[1]), pkb(kbh[2], kbh[3]));
    *(uint2*)(K2o + ob + 128) = make_uint2(pkb(kal[0], kal[1]), pkb(kal[2], kal[3]));
    *(uint2*)(K2o + ob + 192) = make_uint2(pkb(kbl[0], kbl[1]), pkb(kbl[2], kbl[3]));
}

// V fp32 [s][4096] -> split bf16 [h][s][Vh(128)|Vl(128)]
__global__ void __launch_bounds__(256) conv_v(const float* __restrict__ V,
                                              __nv_bfloat16* __restrict__ Vb)
{
    int i = blockIdx.x * 256 + threadIdx.x;   // S*1024
    if (i >= S_LEN * 1024) return;
    int s  = i >> 10;
    int hc = i & 1023;
    int h  = hc >> 5;
    int c4 = (hc & 31) << 2;
    float4 v = ((const float4*)V)[i];
    float in[4] = {v.x, v.y, v.z, v.w};
    __nv_bfloat16 hh[4], ll[4];
#pragma unroll
    for (int j = 0; j < 4; ++j) split2(in[j], hh[j], ll[j]);
    size_t ob = ((size_t)h * S_LEN + s) * HD2 + c4;
    *(uint2*)(Vb + ob)       = make_uint2(pkb(hh[0], hh[1]), pkb(hh[2], hh[3]));
    *(uint2*)(Vb + ob + 128) = make_uint2(pkb(ll[0], ll[1]), pkb(ll[2], ll[3]));
}

// ===========================================================================
// Flash attention v3 (tensor cores, fully split) — validated R7/R8.
// Epilogue now writes A2 [hi|lo] bf16 directly (fuses the O-proj input split).
// ===========================================================================
#define NEG_BIG (-3.0e38f)
#define FROW2  528
#define FROWP  272
#define OFF_K2S  (64 * FROW2)
#define OFF_VS   (OFF_K2S + 2 * 64 * FROW2)
#define OFF_SS   (OFF_VS + 2 * 64 * FROW2)
#define OFF_PS   (OFF_SS + 64 * 68 * 4)
#define OFF_RW   (OFF_PS + 64 * FROWP)
#define FSMEM    (OFF_RW + 3 * 64 * 4)

__device__ __forceinline__ void f_load_kv(uint32_t sb, int buf,
                                          const __nv_bfloat16* __restrict__ K2g,
                                          const __nv_bfloat16* __restrict__ Vg,
                                          int t)
{
    uint32_t kb = sb + OFF_K2S + buf * (64 * FROW2);
    for (int c = t; c < 64 * 32; c += 256) {
        int r = c >> 5, ch = c & 31;
        cp_async16(kb + r * FROW2 + ch * 16,
                   (const char*)K2g + (size_t)r * (HD2 * 2) + ch * 16);
    }
    uint32_t vb = sb + OFF_VS + buf * (64 * FROW2);
    for (int c = t; c < 64 * 32; c += 256) {
        int r = c >> 5, ch = c & 31;
        cp_async16(vb + r * FROW2 + ch * 16,
                   (const char*)Vg + (size_t)r * (HD2 * 2) + ch * 16);
    }
    cp_commit();
}

__global__ void __launch_bounds__(256) flash2(
    const __nv_bfloat16* __restrict__ Q2,
    const __nv_bfloat16* __restrict__ K2g,
    const __nv_bfloat16* __restrict__ Vb,
    __nv_bfloat16* __restrict__ A2out)
{
    extern __shared__ char smraw[];
    const uint32_t sb = smem_u32(smraw);
    float* Ss  = (float*)(smraw + OFF_SS);
    __nv_bfloat16* Ps = (__nv_bfloat16*)(smraw + OFF_PS);
    float* mrow = (float*)(smraw + OFF_RW);
    float* lrow = mrow + 64;
    float* srow = lrow + 64;

    const int h  = blockIdx.x;
    const int qb = (gridDim.y - 1) - blockIdx.y;   // heavy blocks first
    const int q0 = qb * 64;
    const int t = threadIdx.x, wid = t >> 5, lane = t & 31;
    const int wm = (wid >> 2) * 32;
    const int wn = (wid & 3) * 16;
    const int wnv = (wid & 3) * 32;
    const int rA = lane & 15, selA = lane >> 4;
    const int rB = ((lane >> 4) << 3) | (lane & 7), selB = (lane >> 3) & 1;
    const int er = lane >> 2, ec = (lane & 3) << 1;

    const __nv_bfloat16* Qg = Q2 + ((size_t)h * S_LEN + q0) * HD2;
    for (int c = t; c < 64 * 32; c += 256) {
        int r = c >> 5, ch = c & 31;
        cp_async16(sb + r * FROW2 + ch * 16,
                   (const char*)Qg + (size_t)r * (HD2 * 2) + ch * 16);
    }
    cp_commit();
    if (t < 64) { mrow[t] = NEG_BIG; lrow[t] = 0.0f; }

    f_load_kv(sb, 0, K2g + ((size_t)h * S_LEN) * HD2,
              Vb + ((size_t)h * S_LEN) * HD2, t);

    float oacc[2][4][4];
#pragma unroll
    for (int mi = 0; mi < 2; ++mi)
#pragma unroll
        for (int nj = 0; nj < 4; ++nj)
#pragma unroll
            for (int q = 0; q < 4; ++q) oacc[mi][nj][q] = 0.0f;

    for (int kb = 0; kb <= qb; ++kb) {
        const int buf = kb & 1;
        cp_wait<0>();
        __syncthreads();

        if (kb + 1 <= qb)
            f_load_kv(sb, buf ^ 1,
                      K2g + ((size_t)h * S_LEN + (kb + 1) * 64) * HD2,
                      Vb + ((size_t)h * S_LEN + (kb + 1) * 64) * HD2, t);

        const uint32_t kbase = sb + OFF_K2S + buf * (64 * FROW2);
        const uint32_t vbase = sb + OFF_VS + buf * (64 * FROW2);

        float sacc[2][2][4];
#pragma unroll
        for (int mi = 0; mi < 2; ++mi)
#pragma unroll
            for (int nj = 0; nj < 2; ++nj)
#pragma unroll
                for (int q = 0; q < 4; ++q) sacc[mi][nj][q] = 0.0f;

        const uint32_t sAoff[3] = {0u, 0u, 256u};
        const uint32_t sBoff[3] = {0u, 256u, 0u};
#pragma unroll
        for (int ps = 0; ps < 3; ++ps) {
#pragma unroll
            for (int k16 = 0; k16 < 8; ++k16) {
                uint32_t a[2][4], b[4];
#pragma unroll
                for (int mi = 0; mi < 2; ++mi)
                    ldsm_x4(a[mi][0], a[mi][1], a[mi][2], a[mi][3],
                            sb + (uint32_t)((wm + mi * 16 + rA) * FROW2)
                               + sAoff[ps] + k16 * 32 + selA * 16);
                ldsm_x4(b[0], b[1], b[2], b[3],
                        kbase + (uint32_t)((wn + rB) * FROW2)
                              + sBoff[ps] + k16 * 32 + selB * 16);
#pragma unroll
                for (int mi = 0; mi < 2; ++mi)
#pragma unroll
                    for (int nj = 0; nj < 2; ++nj)
                        mma16816(sacc[mi][nj], a[mi], &b[nj << 1]);
            }
        }

        const bool diag = (kb == qb);
#pragma unroll
        for (int mi = 0; mi < 2; ++mi) {
#pragma unroll
            for (int nj = 0; nj < 2; ++nj) {
                int row = wm + mi * 16 + er;
                int col = wn + nj * 8 + ec;
                float v0 = sacc[mi][nj][0], v1 = sacc[mi][nj][1];
                float v2 = sacc[mi][nj][2], v3 = sacc[mi][nj][3];
                if (diag) {
                    if (col > row)     v0 = NEG_BIG;
                    if (col + 1 > row) v1 = NEG_BIG;
                    if (col > row + 8)     v2 = NEG_BIG;
                    if (col + 1 > row + 8) v3 = NEG_BIG;
                }
                Ss[row * 68 + col]       = v0;
                Ss[row * 68 + col + 1]   = v1;
                Ss[(row + 8) * 68 + col]     = v2;
                Ss[(row + 8) * 68 + col + 1] = v3;
            }
        }
        __syncthreads();

        {
            int r  = t >> 2;
            int qd = t & 3;
            float* srw = &Ss[r * 68 + qd * 16];
            __nv_bfloat16* prw = &Ps[r * 136 + qd * 16];
            float vals[16];
            float mx = NEG_BIG;
#pragma unroll
            for (int i = 0; i < 16; ++i) { vals[i] = srw[i]; mx = fmaxf(mx, vals[i]); }
            mx = fmaxf(mx, __shfl_xor_sync(0xffffffffu, mx, 1));
            mx = fmaxf(mx, __shfl_xor_sync(0xffffffffu, mx, 2));
            float mold = mrow[r];
            float mnew = fmaxf(mold, mx);
            float sum = 0.0f;
#pragma unroll
            for (int i = 0; i < 16; ++i) {
                float p = __expf(vals[i] - mnew);
                __nv_bfloat16 ph, pl;
                split2(p, ph, pl);
                prw[i]      = ph;
                prw[i + 64] = pl;
                sum += p;
            }
            sum += __shfl_xor_sync(0xffffffffu, sum, 1);
            sum += __shfl_xor_sync(0xffffffffu, sum, 2);
            float corr = __expf(mold - mnew);
            if (qd == 0) {
                mrow[r] = mnew;
                lrow[r] = lrow[r] * corr + sum;
                srow[r] = corr;
            }
        }
        __syncthreads();

#pragma unroll
        for (int mi = 0; mi < 2; ++mi) {
            float c0 = srow[wm + mi * 16 + er];
            float c1 = srow[wm + mi * 16 + er + 8];
#pragma unroll
            for (int nj = 0; nj < 4; ++nj) {
                oacc[mi][nj][0] *= c0; oacc[mi][nj][1] *= c0;
                oacc[mi][nj][2] *= c1; oacc[mi][nj][3] *= c1;
            }
        }

        const int vkr = ((lane >> 3) & 1) * 8 + (lane & 7);
        const int vnc = (lane >> 4) * 8;
        const uint32_t pAoff[3] = {0u, 0u, 128u};
        const uint32_t pVoff[3] = {0u, 256u, 0u};
#pragma unroll
        for (int ps = 0; ps < 3; ++ps) {
#pragma unroll
            for (int kk = 0; kk < 4; ++kk) {
                uint32_t a[2][4], b0[4], b1[4];
#pragma unroll
                for (int mi = 0; mi < 2; ++mi)
                    ldsm_x4(a[mi][0], a[mi][1], a[mi][2], a[mi][3],
                            sb + OFF_PS + (uint32_t)((wm + mi * 16 + rA) * FROWP)
                               + pAoff[ps] + kk * 32 + selA * 16);
                uint32_t vaddr = vbase + (uint32_t)((kk * 16 + vkr) * FROW2)
                               + pVoff[ps];
                ldsm_x4t(b0[0], b0[1], b0[2], b0[3], vaddr + (wnv + vnc) * 2);
                ldsm_x4t(b1[0], b1[1], b1[2], b1[3], vaddr + (wnv + 16 + vnc) * 2);
#pragma unroll
                for (int mi = 0; mi < 2; ++mi) {
                    mma16816(oacc[mi][0], a[mi], &b0[0]);
                    mma16816(oacc[mi][1], a[mi], &b0[2]);
                    mma16816(oacc[mi][2], a[mi], &b1[0]);
                    mma16816(oacc[mi][3], a[mi], &b1[2]);
                }
            }
        }
    }

    // epilogue: normalize, split fp32->bf16(hi,lo), write A2 [s][hi|lo]
#pragma unroll
    for (int mi = 0; mi < 2; ++mi) {
        float l0 = 1.0f / lrow[wm + mi * 16 + er];
        float l1 = 1.0f / lrow[wm + mi * 16 + er + 8];
#pragma unroll
        for (int nj = 0; nj < 4; ++nj) {
            int col = h * HEADD + wnv + nj * 8 + ec;
            size_t r0 = (size_t)(q0 + wm + mi * 16 + er) * KST2 + col;
            size_t r1 = r0 + (size_t)8 * KST2;
            float x0 = oacc[mi][nj][0] * l0, x1 = oacc[mi][nj][1] * l0;
            float y0 = oacc[mi][nj][2] * l1, y1 = oacc[mi][nj][3] * l1;
            __nv_bfloat16 h0, l0b, h1, l1b;
            split2(x0, h0, l0b); split2(x1, h1, l1b);
            *(uint32_t*)(A2out + r0)        = pkb(h0, h1);
            *(uint32_t*)(A2out + r0 + KSEG) = pkb(l0b, l1b);
            split2(y0, h0, l0b); split2(y1, h1, l1b);
            *(uint32_t*)(A2out + r1)        = pkb(h0, h1);
            *(uint32_t*)(A2out + r1 + KSEG) = pkb(l0b, l1b);
        }
    }
}

// ===========================================================================
// Launch
// ===========================================================================
extern "C" void kernel_launch(void* const* d_in, const int* in_sizes, int n_in,
                              void* d_out, int out_size)
{
    (void)in_sizes; (void)n_in; (void)out_size;

    const float* X   = (const float*)d_in[0];
    const int*   pos = (const int*)d_in[2];
    const float* Wq  = (const float*)d_in[3];
    const float* Wk  = (const float*)d_in[4];
    const float* Wv  = (const float*)d_in[5];
    const float* Wo  = (const float*)d_in[6];
    float* out = (float*)d_out;

    float *Qd, *Kd, *Vd;
    __nv_bfloat16 *A2d, *W2qd, *W2kd, *W2vd, *W2od, *Q2d, *K2d, *Vbd;
    cudaGetSymbolAddress((void**)&Qd, g_Q);
    cudaGetSymbolAddress((void**)&Kd, g_K);
    cudaGetSymbolAddress((void**)&Vd, g_V);
    cudaGetSymbolAddress((void**)&A2d, g_A2);
    cudaGetSymbolAddress((void**)&W2qd, g_W2q);
    cudaGetSymbolAddress((void**)&W2kd, g_W2k);
    cudaGetSymbolAddress((void**)&W2vd, g_W2v);
    cudaGetSymbolAddress((void**)&W2od, g_W2o);
    cudaGetSymbolAddress((void**)&Q2d, g_Q2);
    cudaGetSymbolAddress((void**)&K2d, g_K2a);
    cudaGetSymbolAddress((void**)&Vbd, g_Vb);

    cudaFuncSetAttribute(gemm_mma, cudaFuncAttributeMaxDynamicSharedMemorySize,
                         GSMEM);
    cudaFuncSetAttribute(flash2, cudaFuncAttributeMaxDynamicSharedMemorySize,
                         FSMEM);

    // Splits (all [hi|lo])
    split_hilo<<<(S_LEN * 1024) / 256, 256>>>(X, A2d, S_LEN * 1024);
    split_hilo<<<(HDIM * 1024) / 256, 256>>>(Wq, W2qd, HDIM * 1024);
    split_hilo<<<(HDIM * 1024) / 256, 256>>>(Wk, W2kd, HDIM * 1024);
    split_hilo<<<(HDIM * 1024) / 256, 256>>>(Wv, W2vd, HDIM * 1024);
    split_hilo<<<(HDIM * 1024) / 256, 256>>>(Wo, W2od, HDIM * 1024);

    dim3 ggrid(HDIM / BN, S_LEN / BM);

    gemm_mma<<<ggrid, 128, GSMEM>>>(A2d, W2qd, Qd);
    gemm_mma<<<ggrid, 128, GSMEM>>>(A2d, W2kd, Kd);
    gemm_mma<<<ggrid, 128, GSMEM>>>(A2d, W2vd, Vd);

    // RoPE + head-dim split (fused); V -> split bf16
    rope_split_qk<<<(S_LEN * NHEADS * 16) / 256, 256>>>(Qd, Kd, pos, Q2d, K2d);
    conv_v<<<(S_LEN * 1024) / 256, 256>>>(Vd, Vbd);

    // Tensor-core causal flash attention; epilogue writes split A2 directly
    flash2<<<dim3(NHEADS, S_LEN / 64), 256, FSMEM>>>(Q2d, K2d, Vbd, A2d);

    // O projection (reads A2 written by flash2)
    gemm_mma<<<ggrid, 128, GSMEM>>>(A2d, W2od, out);
}

// round 10
// speedup vs baseline: 4.2728x; 1.1474x over previous
#include <cuda_runtime.h>
#include <cuda_bf16.h>
#include <cuda_fp16.h>
#include <math.h>
#include <stdint.h>

// Problem constants
#define S_LEN  2048
#define HDIM   4096     // hidden = NH*HD
#define NHEADS 32
#define HEADD  128
#define HD2    256      // head-dim split storage: [hi(128) | lo(128)]

#define KSEG   4096     // one split segment
#define KST2   8192     // storage row stride: [seg0 | seg1]
#define SC10   0.0009765625f   // 2^-10

// Scratch (device globals: allocation-free rule)
__device__ float g_Q[S_LEN * HDIM];
__device__ float g_K[S_LEN * HDIM];
__device__ float g_V[S_LEN * HDIM];
__device__ __nv_bfloat16 g_A2[S_LEN * KST2];           // X bf16 [hi|lo] (Q,K gemms)
__device__ __half        g_A2f[S_LEN * KST2];          // X fp16 [xh | xh*2^-10] (V gemm) / attn out (O gemm)
__device__ __nv_bfloat16 g_W2q[HDIM * KST2];           // bf16 [hi|lo]
__device__ __nv_bfloat16 g_W2k[HDIM * KST2];
__device__ __half        g_W2vf[HDIM * KST2];          // fp16 [wh | wl*2^10]
__device__ __half        g_W2of[HDIM * KST2];
__device__ __nv_bfloat16 g_Q2[NHEADS * S_LEN * HD2];   // [h][s][Qh|Ql]
__device__ __nv_bfloat16 g_K2a[NHEADS * S_LEN * HD2];  // [h][s][Kh|Kl]
__device__ __nv_bfloat16 g_Vb[NHEADS * S_LEN * HD2];   // [h][s][Vh|Vl]

// ===========================================================================
// PTX helpers (base PTX only)
// ===========================================================================
__device__ __forceinline__ uint32_t smem_u32(const void* p) {
    uint32_t a;
    asm("{ .reg .u64 t; cvta.to.shared.u64 t, %1; cvt.u32.u64 %0, t; }" : "=r"(a) : "l"(p));
    return a;
}
__device__ __forceinline__ void cp_async16(uint32_t dst, const void* src) {
    asm volatile("cp.async.cg.shared.global [%0], [%1], 16;" :: "r"(dst), "l"(src));
}
__device__ __forceinline__ void cp_commit() {
    asm volatile("cp.async.commit_group;" ::: "memory");
}
template <int N> __device__ __forceinline__ void cp_wait() {
    asm volatile("cp.async.wait_group %0;" :: "n"(N) : "memory");
}
__device__ __forceinline__ void ldsm_x4(uint32_t& r0, uint32_t& r1, uint32_t& r2,
                                        uint32_t& r3, uint32_t addr) {
    asm volatile("ldmatrix.sync.aligned.m8n8.x4.shared.b16 {%0,%1,%2,%3}, [%4];"
                 : "=r"(r0), "=r"(r1), "=r"(r2), "=r"(r3) : "r"(addr));
}
__device__ __forceinline__ void ldsm_x4t(uint32_t& r0, uint32_t& r1, uint32_t& r2,
                                         uint32_t& r3, uint32_t addr) {
    asm volatile("ldmatrix.sync.aligned.m8n8.x4.trans.shared.b16 {%0,%1,%2,%3}, [%4];"
                 : "=r"(r0), "=r"(r1), "=r"(r2), "=r"(r3) : "r"(addr));
}
__device__ __forceinline__ void mma16816(float* c, const uint32_t* a, const uint32_t* b) {
    asm volatile(
        "mma.sync.aligned.m16n8k16.row.col.f32.bf16.bf16.f32 "
        "{%0,%1,%2,%3}, {%4,%5,%6,%7}, {%8,%9}, {%0,%1,%2,%3};"
        : "+f"(c[0]), "+f"(c[1]), "+f"(c[2]), "+f"(c[3])
        : "r"(a[0]), "r"(a[1]), "r"(a[2]), "r"(a[3]), "r"(b[0]), "r"(b[1]));
}
__device__ __forceinline__ void mma16816f(float* c, const uint32_t* a, const uint32_t* b) {
    asm volatile(
        "mma.sync.aligned.m16n8k16.row.col.f32.f16.f16.f32 "
        "{%0,%1,%2,%3}, {%4,%5,%6,%7}, {%8,%9}, {%0,%1,%2,%3};"
        : "+f"(c[0]), "+f"(c[1]), "+f"(c[2]), "+f"(c[3])
        : "r"(a[0]), "r"(a[1]), "r"(a[2]), "r"(a[3]), "r"(b[0]), "r"(b[1]));
}

__device__ __forceinline__ uint32_t pkb(__nv_bfloat16 a, __nv_bfloat16 b) {
    __nv_bfloat162 t = __halves2bfloat162(a, b);
    return *reinterpret_cast<uint32_t*>(&t);
}
__device__ __forceinline__ uint32_t pkh(__half a, __half b) {
    __half2 t = __halves2half2(a, b);
    return *reinterpret_cast<uint32_t*>(&t);
}
__device__ __forceinline__ void split2(float x, __nv_bfloat16& h, __nv_bfloat16& l) {
    h = __float2bfloat16_rn(x);
    l = __float2bfloat16_rn(x - __bfloat162float(h));
}

// ===========================================================================
// X fp32 [R,4096] -> bf16 [hi|lo] (A2) AND fp16 [xh | xh*2^-10] (A2f)
// ===========================================================================
__global__ void __launch_bounds__(256) split_x(const float* __restrict__ src,
                                               __nv_bfloat16* __restrict__ dstb,
                                               __half* __restrict__ dstf,
                                               int total4)
{
    int i = blockIdx.x * 256 + threadIdx.x;
    if (i >= total4) return;
    int row = i >> 10;
    int c4  = (i & 1023) << 2;
    float4 v = ((const float4*)src)[i];
    float in[4] = {v.x, v.y, v.z, v.w};
    __nv_bfloat16 h[4], l[4];
    __half f[4], fs[4];
#pragma unroll
    for (int j = 0; j < 4; ++j) {
        split2(in[j], h[j], l[j]);
        f[j]  = __float2half_rn(in[j]);
        fs[j] = __float2half_rn(in[j] * SC10);
    }
    size_t b = (size_t)row * KST2 + c4;
    *(uint2*)(dstb + b)        = make_uint2(pkb(h[0], h[1]), pkb(h[2], h[3]));
    *(uint2*)(dstb + b + KSEG) = make_uint2(pkb(l[0], l[1]), pkb(l[2], l[3]));
    *(uint2*)(dstf + b)        = make_uint2(pkh(f[0], f[1]), pkh(f[2], f[3]));
    *(uint2*)(dstf + b + KSEG) = make_uint2(pkh(fs[0], fs[1]), pkh(fs[2], fs[3]));
}

// W fp32 -> bf16 [hi|lo]
__global__ void __launch_bounds__(256) split_hilo(const float* __restrict__ src,
                                                  __nv_bfloat16* __restrict__ dst,
                                                  int total4)
{
    int i = blockIdx.x * 256 + threadIdx.x;
    if (i >= total4) return;
    int row = i >> 10;
    int c4  = (i & 1023) << 2;
    float4 v = ((const float4*)src)[i];
    float in[4] = {v.x, v.y, v.z, v.w};
    __nv_bfloat16 h[4], l[4];
#pragma unroll
    for (int j = 0; j < 4; ++j) split2(in[j], h[j], l[j]);
    size_t b = (size_t)row * KST2 + c4;
    *(uint2*)(dst + b)        = make_uint2(pkb(h[0], h[1]), pkb(h[2], h[3]));
    *(uint2*)(dst + b + KSEG) = make_uint2(pkb(l[0], l[1]), pkb(l[2], l[3]));
}

// W fp32 -> fp16 [wh | wl*2^10]
__global__ void __launch_bounds__(256) split_wf16(const float* __restrict__ src,
                                                  __half* __restrict__ dst,
                                                  int total4)
{
    int i = blockIdx.x * 256 + threadIdx.x;
    if (i >= total4) return;
    int row = i >> 10;
    int c4  = (i & 1023) << 2;
    float4 v = ((const float4*)src)[i];
    float in[4] = {v.x, v.y, v.z, v.w};
    __half h[4], l[4];
#pragma unroll
    for (int j = 0; j < 4; ++j) {
        h[j] = __float2half_rn(in[j]);
        l[j] = __float2half_rn((in[j] - __half2float(h[j])) * 1024.0f);
    }
    size_t b = (size_t)row * KST2 + c4;
    *(uint2*)(dst + b)        = make_uint2(pkh(h[0], h[1]), pkh(h[2], h[3]));
    *(uint2*)(dst + b + KSEG) = make_uint2(pkh(l[0], l[1]), pkh(l[2], l[3]));
}

// ===========================================================================
// GEMM common shape: CTA 128x128, BK=32, 128 threads (2x2 warps, 64x64/warp),
// 4-stage cp.async, 2 CTAs/SM.
// ===========================================================================
#define BM 128
#define BN 128
#define BK 32
#define NITER   384                // bf16: 3 segments x 128 iters
#define NITERF  256                // fp16: 2 segments x 128 iters
#define GSTAGES 4
#define ROWB    80
#define ASZ     (BM * ROWB)
#define STAGE   (2 * ASZ)
#define GSMEM   (GSTAGES * STAGE)  // 81920

// bf16 3-term segment select: 0-127 (Ah,Bh), 128-255 (Ah,Bl), 256-383 (Al,Bh)
__device__ __forceinline__ void g_load_stage(uint32_t sb,
                                             const __nv_bfloat16* __restrict__ A2,
                                             const __nv_bfloat16* __restrict__ B2,
                                             int m0, int n0, int j, int t)
{
    const int seg  = j >> 7;
    const int kloc = (j & 127) * BK;
    const int aoff = (seg == 2) ? KSEG : 0;
    const int boff = (seg == 1) ? KSEG : 0;
#pragma unroll
    for (int i = 0; i < 4; ++i) {
        int c   = t + (i << 7);
        int row = c >> 2;
        int kc  = c & 3;
        cp_async16(sb + row * ROWB + kc * 16,
                   A2 + (size_t)(m0 + row) * KST2 + aoff + kloc + kc * 8);
    }
#pragma unroll
    for (int i = 0; i < 4; ++i) {
        int c   = t + (i << 7);
        int row = c >> 2;
        int kc  = c & 3;
        cp_async16(sb + ASZ + row * ROWB + kc * 16,
                   B2 + (size_t)(n0 + row) * KST2 + boff + kloc + kc * 8);
    }
    cp_commit();
}

// fp16 2-term: seg0 (xh, wh), seg1 (xh*2^-10, wl*2^10) — same offset both sides
__device__ __forceinline__ void g_load_stage_f(uint32_t sb,
                                               const __half* __restrict__ A2,
                                               const __half* __restrict__ B2,
                                               int m0, int n0, int j, int t)
{
    const int off  = (j >> 7) ? KSEG : 0;
    const int kloc = (j & 127) * BK;
#pragma unroll
    for (int i = 0; i < 4; ++i) {
        int c   = t + (i << 7);
        int row = c >> 2;
        int kc  = c & 3;
        cp_async16(sb + row * ROWB + kc * 16,
                   A2 + (size_t)(m0 + row) * KST2 + off + kloc + kc * 8);
    }
#pragma unroll
    for (int i = 0; i < 4; ++i) {
        int c   = t + (i << 7);
        int row = c >> 2;
        int kc  = c & 3;
        cp_async16(sb + ASZ + row * ROWB + kc * 16,
                   B2 + (size_t)(n0 + row) * KST2 + off + kloc + kc * 8);
    }
    cp_commit();
}

__global__ void __launch_bounds__(128, 2)
gemm_mma(const __nv_bfloat16* __restrict__ A2,
         const __nv_bfloat16* __restrict__ B2,
         float* __restrict__ C)
{
    extern __shared__ char smraw[];
    const uint32_t base = smem_u32(smraw);
    const int t    = threadIdx.x;
    const int wid  = t >> 5;
    const int lane = t & 31;
    const int m0   = blockIdx.y * BM;
    const int n0   = blockIdx.x * BN;
    const int wm   = (wid >> 1) * 64;
    const int wn   = (wid & 1) * 64;

    const int rA   = lane & 15;
    const int selA = lane >> 4;
    const int rB   = ((lane >> 4) << 3) | (lane & 7);
    const int selB = (lane >> 3) & 1;

    float acc[4][8][4];
#pragma unroll
    for (int mi = 0; mi < 4; ++mi)
#pragma unroll
        for (int nj = 0; nj < 8; ++nj)
#pragma unroll
            for (int q = 0; q < 4; ++q) acc[mi][nj][q] = 0.0f;

#pragma unroll
    for (int it = 0; it < GSTAGES - 1; ++it)
        g_load_stage(base + it * STAGE, A2, B2, m0, n0, it, t);

    for (int it = 0; it < NITER; ++it) {
        const int st = it & (GSTAGES - 1);
        cp_wait<GSTAGES - 2>();
        __syncthreads();

        const uint32_t stA = base + st * STAGE;
        const uint32_t stB = stA + ASZ;

#pragma unroll
        for (int kh = 0; kh < 2; ++kh) {
            uint32_t a[4][4];
#pragma unroll
            for (int mi = 0; mi < 4; ++mi)
                ldsm_x4(a[mi][0], a[mi][1], a[mi][2], a[mi][3],
                        stA + (uint32_t)((wm + mi * 16 + rA) * ROWB
                                         + (kh * 2 + selA) * 16));
            uint32_t b[4][4];
#pragma unroll
            for (int p = 0; p < 4; ++p)
                ldsm_x4(b[p][0], b[p][1], b[p][2], b[p][3],
                        stB + (uint32_t)((wn + p * 16 + rB) * ROWB
                                         + (kh * 2 + selB) * 16));
#pragma unroll
            for (int mi = 0; mi < 4; ++mi) {
#pragma unroll
                for (int p = 0; p < 4; ++p) {
                    mma16816(acc[mi][2 * p],     a[mi], &b[p][0]);
                    mma16816(acc[mi][2 * p + 1], a[mi], &b[p][2]);
                }
            }
        }

        const int j = it + GSTAGES - 1;
        if (j < NITER)
            g_load_stage(base + (j & (GSTAGES - 1)) * STAGE, A2, B2, m0, n0, j, t);
    }

    const int er = lane >> 2;
    const int ec = (lane & 3) << 1;
#pragma unroll
    for (int mi = 0; mi < 4; ++mi) {
#pragma unroll
        for (int nj = 0; nj < 8; ++nj) {
            size_t r0 = (size_t)(m0 + wm + mi * 16 + er) * HDIM
                        + (n0 + wn + nj * 8 + ec);
            *(float2*)&C[r0]            = make_float2(acc[mi][nj][0], acc[mi][nj][1]);
            *(float2*)&C[r0 + 8 * HDIM] = make_float2(acc[mi][nj][2], acc[mi][nj][3]);
        }
    }
}

__global__ void __launch_bounds__(128, 2)
gemm_f16(const __half* __restrict__ A2,
         const __half* __restrict__ B2,
         float* __restrict__ C)
{
    extern __shared__ char smraw[];
    const uint32_t base = smem_u32(smraw);
    const int t    = threadIdx.x;
    const int wid  = t >> 5;
    const int lane = t & 31;
    const int m0   = blockIdx.y * BM;
    const int n0   = blockIdx.x * BN;
    const int wm   = (wid >> 1) * 64;
    const int wn   = (wid & 1) * 64;

    const int rA   = lane & 15;
    const int selA = lane >> 4;
    const int rB   = ((lane >> 4) << 3) | (lane & 7);
    const int selB = (lane >> 3) & 1;

    float acc[4][8][4];
#pragma unroll
    for (int mi = 0; mi < 4; ++mi)
#pragma unroll
        for (int nj = 0; nj < 8; ++nj)
#pragma unroll
            for (int q = 0; q < 4; ++q) acc[mi][nj][q] = 0.0f;

#pragma unroll
    for (int it = 0; it < GSTAGES - 1; ++it)
        g_load_stage_f(base + it * STAGE, A2, B2, m0, n0, it, t);

    for (int it = 0; it < NITERF; ++it) {
        const int st = it & (GSTAGES - 1);
        cp_wait<GSTAGES - 2>();
        __syncthreads();

        const uint32_t stA = base + st * STAGE;
        const uint32_t stB = stA + ASZ;

#pragma unroll
        for (int kh = 0; kh < 2; ++kh) {
            uint32_t a[4][4];
#pragma unroll
            for (int mi = 0; mi < 4; ++mi)
                ldsm_x4(a[mi][0], a[mi][1], a[mi][2], a[mi][3],
                        stA + (uint32_t)((wm + mi * 16 + rA) * ROWB
                                         + (kh * 2 + selA) * 16));
            uint32_t b[4][4];
#pragma unroll
            for (int p = 0; p < 4; ++p)
                ldsm_x4(b[p][0], b[p][1], b[p][2], b[p][3],
                        stB + (uint32_t)((wn + p * 16 + rB) * ROWB
                                         + (kh * 2 + selB) * 16));
#pragma unroll
            for (int mi = 0; mi < 4; ++mi) {
#pragma unroll
                for (int p = 0; p < 4; ++p) {
                    mma16816f(acc[mi][2 * p],     a[mi], &b[p][0]);
                    mma16816f(acc[mi][2 * p + 1], a[mi], &b[p][2]);
                }
            }
        }

        const int j = it + GSTAGES - 1;
        if (j < NITERF)
            g_load_stage_f(base + (j & (GSTAGES - 1)) * STAGE, A2, B2, m0, n0, j, t);
    }

    const int er = lane >> 2;
    const int ec = (lane & 3) << 1;
#pragma unroll
    for (int mi = 0; mi < 4; ++mi) {
#pragma unroll
        for (int nj = 0; nj < 8; ++nj) {
            size_t r0 = (size_t)(m0 + wm + mi * 16 + er) * HDIM
                        + (n0 + wn + nj * 8 + ec);
            *(float2*)&C[r0]            = make_float2(acc[mi][nj][0], acc[mi][nj][1]);
            *(float2*)&C[r0 + 8 * HDIM] = make_float2(acc[mi][nj][2], acc[mi][nj][3]);
        }
    }
}

// ===========================================================================
// Fused RoPE + head-dim split: Q2[h][s][256]=[Qh|Ql]*scale, K2=[Kh|Kl]
// ===========================================================================
#define ATT_SCALE 0.08838834764831843f   // 1/sqrt(128)

__global__ void __launch_bounds__(256) rope_split_qk(
    const float* __restrict__ Q, const float* __restrict__ K,
    const int* __restrict__ pos,
    __nv_bfloat16* __restrict__ Q2, __nv_bfloat16* __restrict__ K2o)
{
    int idx = blockIdx.x * 256 + threadIdx.x;        // S*NH*16
    if (idx >= S_LEN * NHEADS * 16) return;
    int j4 = (idx & 15) << 2;
    int h  = (idx >> 4) & (NHEADS - 1);
    int s  = idx >> 9;
    int p  = pos[s];

    float sn[4], cs[4];
#pragma unroll
    for (int i = 0; i < 4; ++i) {
        float inv = 1.0f / powf(10000.0f, (float)(j4 + i) * (1.0f / 64.0f));
        sincosf((float)p * inv, &sn[i], &cs[i]);
    }

    size_t gb = (size_t)s * HDIM + (size_t)h * HEADD + j4;
    float4 qa4 = *(const float4*)&Q[gb];
    float4 qb4 = *(const float4*)&Q[gb + 64];
    float4 ka4 = *(const float4*)&K[gb];
    float4 kb4 = *(const float4*)&K[gb + 64];
    float qa[4] = {qa4.x, qa4.y, qa4.z, qa4.w};
    float qb[4] = {qb4.x, qb4.y, qb4.z, qb4.w};
    float ka[4] = {ka4.x, ka4.y, ka4.z, ka4.w};
    float kb[4] = {kb4.x, kb4.y, kb4.z, kb4.w};

    __nv_bfloat16 qah[4], qal[4], qbh[4], qbl[4];
    __nv_bfloat16 kah[4], kal[4], kbh[4], kbl[4];
#pragma unroll
    for (int i = 0; i < 4; ++i) {
        float r1 = (qa[i] * cs[i] - qb[i] * sn[i]) * ATT_SCALE;
        float r2 = (qb[i] * cs[i] + qa[i] * sn[i]) * ATT_SCALE;
        split2(r1, qah[i], qal[i]);
        split2(r2, qbh[i], qbl[i]);
        float t1 = ka[i] * cs[i] - kb[i] * sn[i];
        float t2 = kb[i] * cs[i] + ka[i] * sn[i];
        split2(t1, kah[i], kal[i]);
        split2(t2, kbh[i], kbl[i]);
    }

    size_t ob = ((size_t)h * S_LEN + s) * HD2 + j4;
    *(uint2*)(Q2 + ob)       = make_uint2(pkb(qah[0], qah[1]), pkb(qah[2], qah[3]));
    *(uint2*)(Q2 + ob + 64)  = make_uint2(pkb(qbh[0], qbh[1]), pkb(qbh[2], qbh[3]));
    *(uint2*)(Q2 + ob + 128) = make_uint2(pkb(qal[0], qal[1]), pkb(qal[2], qal[3]));
    *(uint2*)(Q2 + ob + 192) = make_uint2(pkb(qbl[0], qbl[1]), pkb(qbl[2], qbl[3]));

    *(uint2*)(K2o + ob)       = make_uint2(pkb(kah[0], kah[1]), pkb(kah[2], kah[3]));
    *(uint2*)(K2o + ob + 64)  = make_uint2(pkb(kbh[0], kbh[1]), pkb(kbh[2], kbh[3]));
    *(uint2*)(K2o + ob + 128) = make_uint2(pkb(kal[0], kal[1]), pkb(kal[2], kal[3]));
    *(uint2*)(K2o + ob + 192) = make_uint2(pkb(kbl[0], kbl[1]), pkb(kbl[2], kbl[3]));
}

// V fp32 [s][4096] -> split bf16 [h][s][Vh(128)|Vl(128)]
__global__ void __launch_bounds__(256) conv_v(const float* __restrict__ V,
                                              __nv_bfloat16* __restrict__ Vb)
{
    int i = blockIdx.x * 256 + threadIdx.x;   // S*1024
    if (i >= S_LEN * 1024) return;
    int s  = i >> 10;
    int hc = i & 1023;
    int h  = hc >> 5;
    int c4 = (hc & 31) << 2;
    float4 v = ((const float4*)V)[i];
    float in[4] = {v.x, v.y, v.z, v.w};
    __nv_bfloat16 hh[4], ll[4];
#pragma unroll
    for (int j = 0; j < 4; ++j) split2(in[j], hh[j], ll[j]);
    size_t ob = ((size_t)h * S_LEN + s) * HD2 + c4;
    *(uint2*)(Vb + ob)       = make_uint2(pkb(hh[0], hh[1]), pkb(hh[2], hh[3]));
    *(uint2*)(Vb + ob + 128) = make_uint2(pkb(ll[0], ll[1]), pkb(ll[2], ll[3]));
}

// ===========================================================================
// Flash attention v3 (tensor cores, fully split) — validated R7-R9.
// Epilogue writes A2f fp16 [xh | xh*2^-10] directly (feeds fp16 O-proj GEMM).
// ===========================================================================
#define NEG_BIG (-3.0e38f)
#define FROW2  528
#define FROWP  272
#define OFF_K2S  (64 * FROW2)
#define OFF_VS   (OFF_K2S + 2 * 64 * FROW2)
#define OFF_SS   (OFF_VS + 2 * 64 * FROW2)
#define OFF_PS   (OFF_SS + 64 * 68 * 4)
#define OFF_RW   (OFF_PS + 64 * FROWP)
#define FSMEM    (OFF_RW + 3 * 64 * 4)

__device__ __forceinline__ void f_load_kv(uint32_t sb, int buf,
                                          const __nv_bfloat16* __restrict__ K2g,
                                          const __nv_bfloat16* __restrict__ Vg,
                                          int t)
{
    uint32_t kb = sb + OFF_K2S + buf * (64 * FROW2);
    for (int c = t; c < 64 * 32; c += 256) {
        int r = c >> 5, ch = c & 31;
        cp_async16(kb + r * FROW2 + ch * 16,
                   (const char*)K2g + (size_t)r * (HD2 * 2) + ch * 16);
    }
    uint32_t vb = sb + OFF_VS + buf * (64 * FROW2);
    for (int c = t; c < 64 * 32; c += 256) {
        int r = c >> 5, ch = c & 31;
        cp_async16(vb + r * FROW2 + ch * 16,
                   (const char*)Vg + (size_t)r * (HD2 * 2) + ch * 16);
    }
    cp_commit();
}

__global__ void __launch_bounds__(256) flash2(
    const __nv_bfloat16* __restrict__ Q2,
    const __nv_bfloat16* __restrict__ K2g,
    const __nv_bfloat16* __restrict__ Vb,
    __half* __restrict__ A2out)
{
    extern __shared__ char smraw[];
    const uint32_t sb = smem_u32(smraw);
    float* Ss  = (float*)(smraw + OFF_SS);
    __nv_bfloat16* Ps = (__nv_bfloat16*)(smraw + OFF_PS);
    float* mrow = (float*)(smraw + OFF_RW);
    float* lrow = mrow + 64;
    float* srow = lrow + 64;

    const int h  = blockIdx.x;
    const int qb = (gridDim.y - 1) - blockIdx.y;   // heavy blocks first
    const int q0 = qb * 64;
    const int t = threadIdx.x, wid = t >> 5, lane = t & 31;
    const int wm = (wid >> 2) * 32;
    const int wn = (wid & 3) * 16;
    const int wnv = (wid & 3) * 32;
    const int rA = lane & 15, selA = lane >> 4;
    const int rB = ((lane >> 4) << 3) | (lane & 7), selB = (lane >> 3) & 1;
    const int er = lane >> 2, ec = (lane & 3) << 1;

    const __nv_bfloat16* Qg = Q2 + ((size_t)h * S_LEN + q0) * HD2;
    for (int c = t; c < 64 * 32; c += 256) {
        int r = c >> 5, ch = c & 31;
        cp_async16(sb + r * FROW2 + ch * 16,
                   (const char*)Qg + (size_t)r * (HD2 * 2) + ch * 16);
    }
    cp_commit();
    if (t < 64) { mrow[t] = NEG_BIG; lrow[t] = 0.0f; }

    f_load_kv(sb, 0, K2g + ((size_t)h * S_LEN) * HD2,
              Vb + ((size_t)h * S_LEN) * HD2, t);

    float oacc[2][4][4];
#pragma unroll
    for (int mi = 0; mi < 2; ++mi)
#pragma unroll
        for (int nj = 0; nj < 4; ++nj)
#pragma unroll
            for (int q = 0; q < 4; ++q) oacc[mi][nj][q] = 0.0f;

    for (int kb = 0; kb <= qb; ++kb) {
        const int buf = kb & 1;
        cp_wait<0>();
        __syncthreads();

        if (kb + 1 <= qb)
            f_load_kv(sb, buf ^ 1,
                      K2g + ((size_t)h * S_LEN + (kb + 1) * 64) * HD2,
                      Vb + ((size_t)h * S_LEN + (kb + 1) * 64) * HD2, t);

        const uint32_t kbase = sb + OFF_K2S + buf * (64 * FROW2);
        const uint32_t vbase = sb + OFF_VS + buf * (64 * FROW2);

        float sacc[2][2][4];
#pragma unroll
        for (int mi = 0; mi < 2; ++mi)
#pragma unroll
            for (int nj = 0; nj < 2; ++nj)
#pragma unroll
                for (int q = 0; q < 4; ++q) sacc[mi][nj][q] = 0.0f;

        const uint32_t sAoff[3] = {0u, 0u, 256u};
        const uint32_t sBoff[3] = {0u, 256u, 0u};
#pragma unroll
        for (int ps = 0; ps < 3; ++ps) {
#pragma unroll
            for (int k16 = 0; k16 < 8; ++k16) {
                uint32_t a[2][4], b[4];
#pragma unroll
                for (int mi = 0; mi < 2; ++mi)
                    ldsm_x4(a[mi][0], a[mi][1], a[mi][2], a[mi][3],
                            sb + (uint32_t)((wm + mi * 16 + rA) * FROW2)
                               + sAoff[ps] + k16 * 32 + selA * 16);
                ldsm_x4(b[0], b[1], b[2], b[3],
                        kbase + (uint32_t)((wn + rB) * FROW2)
                              + sBoff[ps] + k16 * 32 + selB * 16);
#pragma unroll
                for (int mi = 0; mi < 2; ++mi)
#pragma unroll
                    for (int nj = 0; nj < 2; ++nj)
                        mma16816(sacc[mi][nj], a[mi], &b[nj << 1]);
            }
        }

        const bool diag = (kb == qb);
#pragma unroll
        for (int mi = 0; mi < 2; ++mi) {
#pragma unroll
            for (int nj = 0; nj < 2; ++nj) {
                int row = wm + mi * 16 + er;
                int col = wn + nj * 8 + ec;
                float v0 = sacc[mi][nj][0], v1 = sacc[mi][nj][1];
                float v2 = sacc[mi][nj][2], v3 = sacc[mi][nj][3];
                if (diag) {
                    if (col > row)     v0 = NEG_BIG;
                    if (col + 1 > row) v1 = NEG_BIG;
                    if (col > row + 8)     v2 = NEG_BIG;
                    if (col + 1 > row + 8) v3 = NEG_BIG;
                }
                Ss[row * 68 + col]       = v0;
                Ss[row * 68 + col + 1]   = v1;
                Ss[(row + 8) * 68 + col]     = v2;
                Ss[(row + 8) * 68 + col + 1] = v3;
            }
        }
        __syncthreads();

        {
            int r  = t >> 2;
            int qd = t & 3;
            float* srw = &Ss[r * 68 + qd * 16];
            __nv_bfloat16* prw = &Ps[r * 136 + qd * 16];
            float vals[16];
            float mx = NEG_BIG;
#pragma unroll
            for (int i = 0; i < 16; ++i) { vals[i] = srw[i]; mx = fmaxf(mx, vals[i]); }
            mx = fmaxf(mx, __shfl_xor_sync(0xffffffffu, mx, 1));
            mx = fmaxf(mx, __shfl_xor_sync(0xffffffffu, mx, 2));
            float mold = mrow[r];
            float mnew = fmaxf(mold, mx);
            float sum = 0.0f;
#pragma unroll
            for (int i = 0; i < 16; ++i) {
                float p = __expf(vals[i] - mnew);
                __nv_bfloat16 ph, pl;
                split2(p, ph, pl);
                prw[i]      = ph;
                prw[i + 64] = pl;
                sum += p;
            }
            sum += __shfl_xor_sync(0xffffffffu, sum, 1);
            sum += __shfl_xor_sync(0xffffffffu, sum, 2);
            float corr = __expf(mold - mnew);
            if (qd == 0) {
                mrow[r] = mnew;
                lrow[r] = lrow[r] * corr + sum;
                srow[r] = corr;
            }
        }
        __syncthreads();

#pragma unroll
        for (int mi = 0; mi < 2; ++mi) {
            float c0 = srow[wm + mi * 16 + er];
            float c1 = srow[wm + mi * 16 + er + 8];
#pragma unroll
            for (int nj = 0; nj < 4; ++nj) {
                oacc[mi][nj][0] *= c0; oacc[mi][nj][1] *= c0;
                oacc[mi][nj][2] *= c1; oacc[mi][nj][3] *= c1;
            }
        }

        const int vkr = ((lane >> 3) & 1) * 8 + (lane & 7);
        const int vnc = (lane >> 4) * 8;
        const uint32_t pAoff[3] = {0u, 0u, 128u};
        const uint32_t pVoff[3] = {0u, 256u, 0u};
#pragma unroll
        for (int ps = 0; ps < 3; ++ps) {
#pragma unroll
            for (int kk = 0; kk < 4; ++kk) {
                uint32_t a[2][4], b0[4], b1[4];
#pragma unroll
                for (int mi = 0; mi < 2; ++mi)
                    ldsm_x4(a[mi][0], a[mi][1], a[mi][2], a[mi][3],
                            sb + OFF_PS + (uint32_t)((wm + mi * 16 + rA) * FROWP)
                               + pAoff[ps] + kk * 32 + selA * 16);
                uint32_t vaddr = vbase + (uint32_t)((kk * 16 + vkr) * FROW2)
                               + pVoff[ps];
                ldsm_x4t(b0[0], b0[1], b0[2], b0[3], vaddr + (wnv + vnc) * 2);
                ldsm_x4t(b1[0], b1[1], b1[2], b1[3], vaddr + (wnv + 16 + vnc) * 2);
#pragma unroll
                for (int mi = 0; mi < 2; ++mi) {
                    mma16816(oacc[mi][0], a[mi], &b0[0]);
                    mma16816(oacc[mi][1], a[mi], &b0[2]);
                    mma16816(oacc[mi][2], a[mi], &b1[0]);
                    mma16816(oacc[mi][3], a[mi], &b1[2]);
                }
            }
        }
    }

    // epilogue: normalize, write fp16 [xh | xh*2^-10] into A2f
#pragma unroll
    for (int mi = 0; mi < 2; ++mi) {
        float l0 = 1.0f / lrow[wm + mi * 16 + er];
        float l1 = 1.0f / lrow[wm + mi * 16 + er + 8];
#pragma unroll
        for (int nj = 0; nj < 4; ++nj) {
            int col = h * HEADD + wnv + nj * 8 + ec;
            size_t r0 = (size_t)(q0 + wm + mi * 16 + er) * KST2 + col;
            size_t r1 = r0 + (size_t)8 * KST2;
            float x0 = oacc[mi][nj][0] * l0, x1 = oacc[mi][nj][1] * l0;
            float y0 = oacc[mi][nj][2] * l1, y1 = oacc[mi][nj][3] * l1;
            *(uint32_t*)(A2out + r0) =
                pkh(__float2half_rn(x0), __float2half_rn(x1));
            *(uint32_t*)(A2out + r0 + KSEG) =
                pkh(__float2half_rn(x0 * SC10), __float2half_rn(x1 * SC10));
            *(uint32_t*)(A2out + r1) =
                pkh(__float2half_rn(y0), __float2half_rn(y1));
            *(uint32_t*)(A2out + r1 + KSEG) =
                pkh(__float2half_rn(y0 * SC10), __float2half_rn(y1 * SC10));
        }
    }
}

// ===========================================================================
// Launch
// ===========================================================================
extern "C" void kernel_launch(void* const* d_in, const int* in_sizes, int n_in,
                              void* d_out, int out_size)
{
    (void)in_sizes; (void)n_in; (void)out_size;

    const float* X   = (const float*)d_in[0];
    const int*   pos = (const int*)d_in[2];
    const float* Wq  = (const float*)d_in[3];
    const float* Wk  = (const float*)d_in[4];
    const float* Wv  = (const float*)d_in[5];
    const float* Wo  = (const float*)d_in[6];
    float* out = (float*)d_out;

    float *Qd, *Kd, *Vd;
    __nv_bfloat16 *A2d, *W2qd, *W2kd, *Q2d, *K2d, *Vbd;
    __half *A2fd, *W2vfd, *W2ofd;
    cudaGetSymbolAddress((void**)&Qd, g_Q);
    cudaGetSymbolAddress((void**)&Kd, g_K);
    cudaGetSymbolAddress((void**)&Vd, g_V);
    cudaGetSymbolAddress((void**)&A2d, g_A2);
    cudaGetSymbolAddress((void**)&A2fd, g_A2f);
    cudaGetSymbolAddress((void**)&W2qd, g_W2q);
    cudaGetSymbolAddress((void**)&W2kd, g_W2k);
    cudaGetSymbolAddress((void**)&W2vfd, g_W2vf);
    cudaGetSymbolAddress((void**)&W2ofd, g_W2of);
    cudaGetSymbolAddress((void**)&Q2d, g_Q2);
    cudaGetSymbolAddress((void**)&K2d, g_K2a);
    cudaGetSymbolAddress((void**)&Vbd, g_Vb);

    cudaFuncSetAttribute(gemm_mma, cudaFuncAttributeMaxDynamicSharedMemorySize,
                         GSMEM);
    cudaFuncSetAttribute(gemm_f16, cudaFuncAttributeMaxDynamicSharedMemorySize,
                         GSMEM);
    cudaFuncSetAttribute(flash2, cudaFuncAttributeMaxDynamicSharedMemorySize,
                         FSMEM);

    // Splits
    split_x<<<(S_LEN * 1024) / 256, 256>>>(X, A2d, A2fd, S_LEN * 1024);
    split_hilo<<<(HDIM * 1024) / 256, 256>>>(Wq, W2qd, HDIM * 1024);
    split_hilo<<<(HDIM * 1024) / 256, 256>>>(Wk, W2kd, HDIM * 1024);
    split_wf16<<<(HDIM * 1024) / 256, 256>>>(Wv, W2vfd, HDIM * 1024);
    split_wf16<<<(HDIM * 1024) / 256, 256>>>(Wo, W2ofd, HDIM * 1024);

    dim3 ggrid(HDIM / BN, S_LEN / BM);

    // Q,K: bf16 3-term (score path needs it); V: fp16 2-term
    gemm_mma<<<ggrid, 128, GSMEM>>>(A2d, W2qd, Qd);
    gemm_mma<<<ggrid, 128, GSMEM>>>(A2d, W2kd, Kd);
    gemm_f16<<<ggrid, 128, GSMEM>>>(A2fd, W2vfd, Vd);

    // RoPE + head-dim split (fused); V -> split bf16
    rope_split_qk<<<(S_LEN * NHEADS * 16) / 256, 256>>>(Qd, Kd, pos, Q2d, K2d);
    conv_v<<<(S_LEN * 1024) / 256, 256>>>(Vd, Vbd);

    // Tensor-core causal flash attention; epilogue writes fp16 A2f directly
    flash2<<<dim3(NHEADS, S_LEN / 64), 256, FSMEM>>>(Q2d, K2d, Vbd, A2fd);

    // O projection: fp16 2-term
    gemm_f16<<<ggrid, 128, GSMEM>>>(A2fd, W2ofd, out);
}